// round 1
// baseline (speedup 1.0000x reference)
#include <cuda_runtime.h>
#include <math.h>

#define N_NODES  50000
#define N_EDGESC 800000
#define ND       64
#define ED       32
#define MSG      128
#define HID      256
#define N_AGENTS 25000

// ---------------- scratch (static device globals; no runtime alloc) ----------------
__device__ float        g_Ps[(size_t)N_NODES * HID];      // node@W1a + b1   (51.2 MB)
__device__ float        g_Pr[(size_t)N_NODES * HID];      // node@W1b        (51.2 MB)
__device__ float        g_msg[(size_t)N_EDGESC * MSG];    // per-edge messages (409.6 MB worst case)
__device__ float        g_lg[N_EDGESC];                   // logits, then exp(logit - max)
__device__ int          g_eidx[N_EDGESC];                 // compacted edge ids
__device__ int          g_cnt;                            // number of live edges
__device__ unsigned int g_segmax[N_AGENTS];               // float-as-ordered-uint max
__device__ float        g_denom[N_AGENTS];
__device__ float        g_aggr[(size_t)N_AGENTS * MSG];   // 12.8 MB

// ordered-uint mapping for float atomicMax
__device__ __forceinline__ unsigned f2ord(float f) {
    unsigned u = __float_as_uint(f);
    return (u & 0x80000000u) ? ~u : (u | 0x80000000u);
}
__device__ __forceinline__ float ord2f(unsigned o) {
    unsigned u = (o & 0x80000000u) ? (o & 0x7fffffffu) : ~o;
    return __uint_as_float(u);
}

// ---------------- init ----------------
__global__ void k_init() {
    int i = blockIdx.x * blockDim.x + threadIdx.x;
    int stride = gridDim.x * blockDim.x;
    for (int j = i; j < N_AGENTS * MSG; j += stride) g_aggr[j] = 0.f;
    if (i < N_AGENTS) { g_segmax[i] = 0u; g_denom[i] = 0.f; }
    if (i == 0) g_cnt = 0;
}

// ---------------- compaction: keep only edges whose receiver is an agent ----------------
__global__ void k_compact(const int* __restrict__ rcv) {
    int e = blockIdx.x * blockDim.x + threadIdx.x;
    if (e < N_EDGESC && rcv[e] < N_AGENTS) {
        int p = atomicAdd(&g_cnt, 1);
        g_eidx[p] = e;
    }
}

// ---------------- node projection: Ps = node@W1[0:64]+b1, Pr = node@W1[64:128] ----------------
__global__ __launch_bounds__(256, 2) void k_nodeproj(
    const float* __restrict__ nf, const float* __restrict__ W1, const float* __restrict__ b1)
{
    __shared__ float sA[64][ND];   // 16 KB
    int n0 = blockIdx.x * 64;
    const float* W = W1 + (blockIdx.y ? 64 * HID : 0);
    float* out = blockIdx.y ? g_Pr : g_Ps;
    int tid = threadIdx.x;

    for (int j = tid; j < 64 * (ND / 4); j += 256) {
        int r = j >> 4, c4 = j & 15;
        int n = n0 + r;
        float4 v = (n < N_NODES) ? __ldg((const float4*)nf + (size_t)n * (ND / 4) + c4)
                                 : make_float4(0.f, 0.f, 0.f, 0.f);
        *(float4*)&sA[r][c4 * 4] = v;
    }
    __syncthreads();

    int rg = tid >> 5, lane = tid & 31;
    int r0 = rg * 8, c0 = lane * 8;
    float acc[8][8];
    {
        float bv[8];
        if (blockIdx.y == 0) {
            float4 u0 = __ldg((const float4*)(b1 + c0));
            float4 u1 = __ldg((const float4*)(b1 + c0 + 4));
            bv[0]=u0.x; bv[1]=u0.y; bv[2]=u0.z; bv[3]=u0.w; bv[4]=u1.x; bv[5]=u1.y; bv[6]=u1.z; bv[7]=u1.w;
        } else {
            #pragma unroll
            for (int j = 0; j < 8; j++) bv[j] = 0.f;
        }
        #pragma unroll
        for (int i = 0; i < 8; i++)
            #pragma unroll
            for (int j = 0; j < 8; j++) acc[i][j] = bv[j];
    }

    for (int k4 = 0; k4 < ND / 4; k4++) {
        float wv[4][8];
        #pragma unroll
        for (int kk = 0; kk < 4; kk++) {
            const float* wr = W + (k4 * 4 + kk) * HID + c0;
            float4 u0 = __ldg((const float4*)wr);
            float4 u1 = __ldg((const float4*)(wr + 4));
            wv[kk][0]=u0.x; wv[kk][1]=u0.y; wv[kk][2]=u0.z; wv[kk][3]=u0.w;
            wv[kk][4]=u1.x; wv[kk][5]=u1.y; wv[kk][6]=u1.z; wv[kk][7]=u1.w;
        }
        #pragma unroll
        for (int i = 0; i < 8; i++) {
            float4 a = *(float4*)&sA[r0 + i][k4 * 4];
            float av[4] = {a.x, a.y, a.z, a.w};
            #pragma unroll
            for (int kk = 0; kk < 4; kk++)
                #pragma unroll
                for (int j = 0; j < 8; j++) acc[i][j] += av[kk] * wv[kk][j];
        }
    }

    #pragma unroll
    for (int i = 0; i < 8; i++) {
        int n = n0 + r0 + i;
        if (n < N_NODES) {
            *(float4*)&out[(size_t)n * HID + c0]     = make_float4(acc[i][0], acc[i][1], acc[i][2], acc[i][3]);
            *(float4*)&out[(size_t)n * HID + c0 + 4] = make_float4(acc[i][4], acc[i][5], acc[i][6], acc[i][7]);
        }
    }
}

// ---------------- fused edge MLP: h=relu(Ps[s]+Pr[r]+E@W1c), msg=relu(h@W2+b2), logit, segmax ----------------
// dynamic smem: sH 64x256 f32 | sE 64x32 f32 | sS/sR/sEg 64 ints each = 74496 B
#define SMEM_B ((64 * HID + 64 * ED) * 4 + 3 * 64 * 4)

__global__ __launch_bounds__(256, 2) void k_edge_mlp(
    const float* __restrict__ ef, const float* __restrict__ W1,
    const float* __restrict__ W2, const float* __restrict__ b2,
    const float* __restrict__ wg, const float* __restrict__ bg,
    const int* __restrict__ snd, const int* __restrict__ rcv)
{
    extern __shared__ float smem[];
    float* sH = smem;                  // 64 x 256
    float* sE = smem + 64 * HID;       // 64 x 32
    int* sS  = (int*)(sE + 64 * ED);
    int* sR  = sS + 64;
    int* sEg = sR + 64;

    int cnt = g_cnt;
    int ci0 = blockIdx.x * 64;
    if (ci0 >= cnt) return;
    int nE = min(64, cnt - ci0);
    int tid = threadIdx.x;

    if (tid < 64) {
        int e = (tid < nE) ? g_eidx[ci0 + tid] : g_eidx[ci0];
        sEg[tid] = e;
        sS[tid] = snd[e];
        sR[tid] = rcv[e];
    }
    __syncthreads();

    // base = Ps[s] + Pr[r]  (b1 folded into Ps)
    for (int j = tid; j < 64 * (HID / 4); j += 256) {
        int r = j >> 6, c4 = j & 63;
        float4 a = __ldg((const float4*)g_Ps + (size_t)sS[r] * (HID / 4) + c4);
        float4 b = __ldg((const float4*)g_Pr + (size_t)sR[r] * (HID / 4) + c4);
        *(float4*)&sH[r * HID + c4 * 4] = make_float4(a.x + b.x, a.y + b.y, a.z + b.z, a.w + b.w);
    }
    // edge features
    for (int j = tid; j < 64 * (ED / 4); j += 256) {
        int r = j >> 3, c4 = j & 7;
        ((float4*)sE)[r * (ED / 4) + c4] = __ldg((const float4*)ef + (size_t)sEg[r] * (ED / 4) + c4);
    }
    __syncthreads();

    int rg = tid >> 5, lane = tid & 31;
    int r0 = rg * 8;

    // ---- GEMM1: h = relu(base + E @ W1c), tile 64x256, K=32 ----
    {
        int c0 = lane * 8;
        float acc[8][8];
        #pragma unroll
        for (int i = 0; i < 8; i++) {
            float4 v0 = *(float4*)&sH[(r0 + i) * HID + c0];
            float4 v1 = *(float4*)&sH[(r0 + i) * HID + c0 + 4];
            acc[i][0]=v0.x; acc[i][1]=v0.y; acc[i][2]=v0.z; acc[i][3]=v0.w;
            acc[i][4]=v1.x; acc[i][5]=v1.y; acc[i][6]=v1.z; acc[i][7]=v1.w;
        }
        const float* W1c = W1 + 128 * HID;
        for (int k4 = 0; k4 < ED / 4; k4++) {
            float wv[4][8];
            #pragma unroll
            for (int kk = 0; kk < 4; kk++) {
                const float* wr = W1c + (k4 * 4 + kk) * HID + c0;
                float4 u0 = __ldg((const float4*)wr);
                float4 u1 = __ldg((const float4*)(wr + 4));
                wv[kk][0]=u0.x; wv[kk][1]=u0.y; wv[kk][2]=u0.z; wv[kk][3]=u0.w;
                wv[kk][4]=u1.x; wv[kk][5]=u1.y; wv[kk][6]=u1.z; wv[kk][7]=u1.w;
            }
            #pragma unroll
            for (int i = 0; i < 8; i++) {
                float4 a = *(float4*)&sE[(r0 + i) * ED + k4 * 4];
                float av[4] = {a.x, a.y, a.z, a.w};
                #pragma unroll
                for (int kk = 0; kk < 4; kk++)
                    #pragma unroll
                    for (int j = 0; j < 8; j++) acc[i][j] += av[kk] * wv[kk][j];
            }
        }
        // relu + writeback (own tile only: no cross-thread hazard before sync)
        #pragma unroll
        for (int i = 0; i < 8; i++) {
            #pragma unroll
            for (int j = 0; j < 8; j++) acc[i][j] = fmaxf(acc[i][j], 0.f);
            *(float4*)&sH[(r0 + i) * HID + c0]     = make_float4(acc[i][0], acc[i][1], acc[i][2], acc[i][3]);
            *(float4*)&sH[(r0 + i) * HID + c0 + 4] = make_float4(acc[i][4], acc[i][5], acc[i][6], acc[i][7]);
        }
    }
    __syncthreads();

    // ---- GEMM2: msg = relu(h @ W2 + b2), tile 64x128, K=256 ----
    {
        int c0 = lane * 4;
        float acc[8][4];
        {
            float4 u = __ldg((const float4*)(b2 + c0));
            #pragma unroll
            for (int i = 0; i < 8; i++) { acc[i][0]=u.x; acc[i][1]=u.y; acc[i][2]=u.z; acc[i][3]=u.w; }
        }
        for (int k4 = 0; k4 < HID / 4; k4++) {
            float wv[4][4];
            #pragma unroll
            for (int kk = 0; kk < 4; kk++) {
                float4 u = __ldg((const float4*)(W2 + (k4 * 4 + kk) * MSG + c0));
                wv[kk][0]=u.x; wv[kk][1]=u.y; wv[kk][2]=u.z; wv[kk][3]=u.w;
            }
            #pragma unroll
            for (int i = 0; i < 8; i++) {
                float4 a = *(float4*)&sH[(r0 + i) * HID + k4 * 4];
                float av[4] = {a.x, a.y, a.z, a.w};
                #pragma unroll
                for (int kk = 0; kk < 4; kk++)
                    #pragma unroll
                    for (int j = 0; j < 4; j++) acc[i][j] += av[kk] * wv[kk][j];
            }
        }
        #pragma unroll
        for (int i = 0; i < 8; i++)
            #pragma unroll
            for (int j = 0; j < 4; j++) acc[i][j] = fmaxf(acc[i][j], 0.f);

        // gate logits: per-row dot(msg, w_gate) reduced across the warp
        float4 wg4 = __ldg((const float4*)(wg + c0));
        float part[8];
        #pragma unroll
        for (int i = 0; i < 8; i++)
            part[i] = acc[i][0]*wg4.x + acc[i][1]*wg4.y + acc[i][2]*wg4.z + acc[i][3]*wg4.w;
        #pragma unroll
        for (int off = 16; off > 0; off >>= 1)
            #pragma unroll
            for (int i = 0; i < 8; i++) part[i] += __shfl_xor_sync(0xffffffffu, part[i], off);

        float bgv = __ldg(bg);
        #pragma unroll
        for (int i = 0; i < 8; i++) {
            int row = r0 + i;
            if (lane == i && row < nE) {
                float lgv = part[i] + bgv;
                g_lg[ci0 + row] = lgv;
                atomicMax(&g_segmax[sR[row]], f2ord(lgv));
            }
        }
        // store messages
        #pragma unroll
        for (int i = 0; i < 8; i++) {
            int row = r0 + i;
            if (row < nE)
                *(float4*)&g_msg[(size_t)(ci0 + row) * MSG + c0] =
                    make_float4(acc[i][0], acc[i][1], acc[i][2], acc[i][3]);
        }
    }
}

// ---------------- softmax numerator + denominator ----------------
__global__ void k_softmax_e(const int* __restrict__ rcv) {
    int ci = blockIdx.x * blockDim.x + threadIdx.x;
    if (ci >= g_cnt) return;
    int e = g_eidx[ci];
    int r = rcv[e];
    float m = ord2f(g_segmax[r]);
    float ex = expf(g_lg[ci] - m);
    g_lg[ci] = ex;
    atomicAdd(&g_denom[r], ex);
}

// ---------------- weighted scatter: aggr[r] += (e/denom) * msg, 32 lanes/edge, red.v4 ----------------
__global__ void k_aggr(const int* __restrict__ rcv) {
    int idx = blockIdx.x * blockDim.x + threadIdx.x;
    int lane = idx & 31;
    int ci = idx >> 5;
    if (ci >= g_cnt) return;
    int e = g_eidx[ci];
    int r = rcv[e];
    float w = g_lg[ci] / (g_denom[r] + 1e-9f);
    float4 m = *(const float4*)&g_msg[(size_t)ci * MSG + lane * 4];
    float* dst = &g_aggr[(size_t)r * MSG + lane * 4];
    asm volatile("red.global.add.v4.f32 [%0], {%1,%2,%3,%4};"
                 :: "l"(dst), "f"(w * m.x), "f"(w * m.y), "f"(w * m.z), "f"(w * m.w)
                 : "memory");
}

// ---------------- agent MLP head: relu(x@Wh1+b)-> relu(@Wh2+b) -> tanh(@Wo+b) ----------------
#define SMEM_E (2 * 64 * HID * 4)

__global__ __launch_bounds__(256) void k_agent(
    const float* __restrict__ Wh1, const float* __restrict__ bh1,
    const float* __restrict__ Wh2, const float* __restrict__ bh2,
    const float* __restrict__ Wo,  const float* __restrict__ bo,
    float* __restrict__ out)
{
    extern __shared__ float smem[];
    float* s1 = smem;              // h1: 64 x 256
    float* s2 = smem + 64 * HID;   // x (64x128 packed), then h2 (64x256)

    int a0 = blockIdx.x * 64;
    int tid = threadIdx.x;
    int rg = tid >> 5, lane = tid & 31;
    int r0 = rg * 8;

    // load x = aggr rows (zero-pad OOB)
    for (int j = tid; j < 64 * (MSG / 4); j += 256) {
        int r = j >> 5, c4 = j & 31;
        int a = a0 + r;
        float4 v = (a < N_AGENTS) ? *((const float4*)g_aggr + (size_t)a * (MSG / 4) + c4)
                                  : make_float4(0.f, 0.f, 0.f, 0.f);
        *(float4*)&s2[r * MSG + c4 * 4] = v;
    }
    __syncthreads();

    // h1 = relu(x @ Wh1 + bh1): 64x256, K=128
    {
        int c0 = lane * 8;
        float acc[8][8];
        {
            float4 u0 = __ldg((const float4*)(bh1 + c0));
            float4 u1 = __ldg((const float4*)(bh1 + c0 + 4));
            float bv[8] = {u0.x,u0.y,u0.z,u0.w,u1.x,u1.y,u1.z,u1.w};
            #pragma unroll
            for (int i = 0; i < 8; i++)
                #pragma unroll
                for (int j = 0; j < 8; j++) acc[i][j] = bv[j];
        }
        for (int k4 = 0; k4 < MSG / 4; k4++) {
            float wv[4][8];
            #pragma unroll
            for (int kk = 0; kk < 4; kk++) {
                const float* wr = Wh1 + (k4 * 4 + kk) * HID + c0;
                float4 u0 = __ldg((const float4*)wr);
                float4 u1 = __ldg((const float4*)(wr + 4));
                wv[kk][0]=u0.x; wv[kk][1]=u0.y; wv[kk][2]=u0.z; wv[kk][3]=u0.w;
                wv[kk][4]=u1.x; wv[kk][5]=u1.y; wv[kk][6]=u1.z; wv[kk][7]=u1.w;
            }
            #pragma unroll
            for (int i = 0; i < 8; i++) {
                float4 a = *(float4*)&s2[(r0 + i) * MSG + k4 * 4];
                float av[4] = {a.x, a.y, a.z, a.w};
                #pragma unroll
                for (int kk = 0; kk < 4; kk++)
                    #pragma unroll
                    for (int j = 0; j < 8; j++) acc[i][j] += av[kk] * wv[kk][j];
            }
        }
        #pragma unroll
        for (int i = 0; i < 8; i++) {
            #pragma unroll
            for (int j = 0; j < 8; j++) acc[i][j] = fmaxf(acc[i][j], 0.f);
            *(float4*)&s1[(r0 + i) * HID + c0]     = make_float4(acc[i][0], acc[i][1], acc[i][2], acc[i][3]);
            *(float4*)&s1[(r0 + i) * HID + c0 + 4] = make_float4(acc[i][4], acc[i][5], acc[i][6], acc[i][7]);
        }
    }
    __syncthreads();

    // h2 = relu(h1 @ Wh2 + bh2): 64x256, K=256 (x in s2 is dead -> overwrite s2)
    {
        int c0 = lane * 8;
        float acc[8][8];
        {
            float4 u0 = __ldg((const float4*)(bh2 + c0));
            float4 u1 = __ldg((const float4*)(bh2 + c0 + 4));
            float bv[8] = {u0.x,u0.y,u0.z,u0.w,u1.x,u1.y,u1.z,u1.w};
            #pragma unroll
            for (int i = 0; i < 8; i++)
                #pragma unroll
                for (int j = 0; j < 8; j++) acc[i][j] = bv[j];
        }
        for (int k4 = 0; k4 < HID / 4; k4++) {
            float wv[4][8];
            #pragma unroll
            for (int kk = 0; kk < 4; kk++) {
                const float* wr = Wh2 + (k4 * 4 + kk) * HID + c0;
                float4 u0 = __ldg((const float4*)wr);
                float4 u1 = __ldg((const float4*)(wr + 4));
                wv[kk][0]=u0.x; wv[kk][1]=u0.y; wv[kk][2]=u0.z; wv[kk][3]=u0.w;
                wv[kk][4]=u1.x; wv[kk][5]=u1.y; wv[kk][6]=u1.z; wv[kk][7]=u1.w;
            }
            #pragma unroll
            for (int i = 0; i < 8; i++) {
                float4 a = *(float4*)&s1[(r0 + i) * HID + k4 * 4];
                float av[4] = {a.x, a.y, a.z, a.w};
                #pragma unroll
                for (int kk = 0; kk < 4; kk++)
                    #pragma unroll
                    for (int j = 0; j < 8; j++) acc[i][j] += av[kk] * wv[kk][j];
            }
        }
        __syncthreads();  // everyone done reading x region before overwrite (h1 reads fine; x overlap safety)
        #pragma unroll
        for (int i = 0; i < 8; i++) {
            #pragma unroll
            for (int j = 0; j < 8; j++) acc[i][j] = fmaxf(acc[i][j], 0.f);
            *(float4*)&s2[(r0 + i) * HID + c0]     = make_float4(acc[i][0], acc[i][1], acc[i][2], acc[i][3]);
            *(float4*)&s2[(r0 + i) * HID + c0 + 4] = make_float4(acc[i][4], acc[i][5], acc[i][6], acc[i][7]);
        }
    }
    __syncthreads();

    // out = tanh(h2 @ Wo + bo), one warp handles 8 rows
    {
        float wv[8];
        #pragma unroll
        for (int j = 0; j < 8; j++) wv[j] = __ldg(Wo + lane + 32 * j);
        float bov = __ldg(bo);
        #pragma unroll
        for (int i = 0; i < 8; i++) {
            int row = r0 + i;
            float p = 0.f;
            #pragma unroll
            for (int j = 0; j < 8; j++) p += s2[row * HID + lane + 32 * j] * wv[j];
            #pragma unroll
            for (int off = 16; off > 0; off >>= 1) p += __shfl_xor_sync(0xffffffffu, p, off);
            int a = a0 + row;
            if (lane == 0 && a < N_AGENTS) out[a] = tanhf(p + bov);
        }
    }
}

// ---------------- launch ----------------
extern "C" void kernel_launch(void* const* d_in, const int* in_sizes, int n_in,
                              void* d_out, int out_size)
{
    const float* node = (const float*)d_in[0];
    const float* ef   = (const float*)d_in[1];
    const float* W1   = (const float*)d_in[2];
    const float* b1   = (const float*)d_in[3];
    const float* W2   = (const float*)d_in[4];
    const float* b2   = (const float*)d_in[5];
    const float* wg   = (const float*)d_in[6];
    const float* bg   = (const float*)d_in[7];
    const float* Wh1  = (const float*)d_in[8];
    const float* bh1  = (const float*)d_in[9];
    const float* Wh2  = (const float*)d_in[10];
    const float* bh2  = (const float*)d_in[11];
    const float* Wo   = (const float*)d_in[12];
    const float* bo   = (const float*)d_in[13];
    const int*   snd  = (const int*)d_in[14];
    const int*   rcv  = (const int*)d_in[15];
    float* out = (float*)d_out;

    cudaFuncSetAttribute(k_edge_mlp, cudaFuncAttributeMaxDynamicSharedMemorySize, SMEM_B);
    cudaFuncSetAttribute(k_agent,    cudaFuncAttributeMaxDynamicSharedMemorySize, SMEM_E);

    k_init<<<12500, 256>>>();
    k_compact<<<(N_EDGESC + 255) / 256, 256>>>(rcv);
    dim3 gA((N_NODES + 63) / 64, 2);
    k_nodeproj<<<gA, 256>>>(node, W1, b1);
    k_edge_mlp<<<N_EDGESC / 64, 256, SMEM_B>>>(ef, W1, W2, b2, wg, bg, snd, rcv);
    k_softmax_e<<<(N_EDGESC + 255) / 256, 256>>>(rcv);
    k_aggr<<<(N_EDGESC * 32) / 256, 256>>>(rcv);
    k_agent<<<(N_AGENTS + 63) / 64, 256, SMEM_E>>>(Wh1, bh1, Wh2, bh2, Wo, bo, out);
}

// round 5
// speedup vs baseline: 1.4400x; 1.4400x over previous
#include <cuda_runtime.h>
#include <math.h>
#include <stdint.h>

#define N_NODES  50000
#define N_EDGESC 800000
#define ND       64
#define ED       32
#define MSG      128
#define HID      256
#define N_AGENTS 25000
#define KTOT     160          // 2*ND + ED

// ---------------- scratch ----------------
__device__ float        g_msg[(size_t)N_EDGESC * MSG];
__device__ float        g_lg[N_EDGESC];
__device__ int          g_eidx[N_EDGESC];
__device__ int          g_cnt;
__device__ unsigned int g_segmax[N_AGENTS];
__device__ float        g_denom[N_AGENTS];
__device__ float        g_aggr[(size_t)N_AGENTS * MSG];

__device__ __forceinline__ unsigned f2ord(float f) {
    unsigned u = __float_as_uint(f);
    return (u & 0x80000000u) ? ~u : (u | 0x80000000u);
}
__device__ __forceinline__ float ord2f(unsigned o) {
    unsigned u = (o & 0x80000000u) ? (o & 0x7fffffffu) : ~o;
    return __uint_as_float(u);
}
__device__ __forceinline__ float tf32r(float x) {
    uint32_t u;
    asm("cvt.rna.tf32.f32 %0, %1;" : "=r"(u) : "f"(x));
    return __uint_as_float(u);
}

// warp mma: D(16x8,f32) += A(16x8,tf32) * B(8x8,tf32)
__device__ __forceinline__ void mma168(float* d, const uint32_t* a, const uint32_t* b) {
    asm volatile(
        "mma.sync.aligned.m16n8k8.row.col.f32.tf32.tf32.f32 "
        "{%0,%1,%2,%3}, {%4,%5,%6,%7}, {%8,%9}, {%0,%1,%2,%3};"
        : "+f"(d[0]), "+f"(d[1]), "+f"(d[2]), "+f"(d[3])
        : "r"(a[0]), "r"(a[1]), "r"(a[2]), "r"(a[3]), "r"(b[0]), "r"(b[1]));
}

// ---------------- init / compact ----------------
__global__ void k_init() {
    int i = blockIdx.x * blockDim.x + threadIdx.x;
    int stride = gridDim.x * blockDim.x;
    for (int j = i; j < N_AGENTS * MSG; j += stride) g_aggr[j] = 0.f;
    if (i < N_AGENTS) { g_segmax[i] = 0u; g_denom[i] = 0.f; }
    if (i == 0) g_cnt = 0;
}
__global__ void k_compact(const int* __restrict__ rcv) {
    int e = blockIdx.x * blockDim.x + threadIdx.x;
    if (e < N_EDGESC && rcv[e] < N_AGENTS) {
        int p = atomicAdd(&g_cnt, 1);
        g_eidx[p] = e;
    }
}

// ---------------- fused edge MLP on mma.sync tf32 ----------------
// smem (bytes):
#define SA_STR   164                    // A tile row stride (floats)
#define SH_STR   260                    // h tile row stride (floats)
#define W1_STR   264                    // W chunk row stride GEMM1 (floats)
#define W2_STR   136                    // W chunk row stride GEMM2 (floats)
#define OFF_AH   0                      // union: sA 128*164*4=83968 / sH 128*260*4=133120
#define OFF_W    133120                 // 32*264*4 = 33792
#define OFF_EG   166912
#define OFF_S    167424
#define OFF_R    167936
#define OFF_B1   168448                 // 256 f
#define OFF_B2   169472                 // 128 f
#define OFF_WG   169984                 // 128 f
#define OFF_GATE 170496                 // 256 f
#define SMEM_EDGE 171520

__global__ __launch_bounds__(512, 1) void k_edge_mma(
    const float* __restrict__ nf, const float* __restrict__ ef,
    const float* __restrict__ W1, const float* __restrict__ b1,
    const float* __restrict__ W2, const float* __restrict__ b2,
    const float* __restrict__ wg, const float* __restrict__ bg,
    const int* __restrict__ snd, const int* __restrict__ rcv)
{
    extern __shared__ char smem[];
    float* sA = (float*)(smem + OFF_AH);
    float* sH = (float*)(smem + OFF_AH);
    float* sW = (float*)(smem + OFF_W);
    int*   sEg = (int*)(smem + OFF_EG);
    int*   sS  = (int*)(smem + OFF_S);
    int*   sR  = (int*)(smem + OFF_R);
    float* sB1 = (float*)(smem + OFF_B1);
    float* sB2 = (float*)(smem + OFF_B2);
    float* sWg = (float*)(smem + OFF_WG);
    float* sGate = (float*)(smem + OFF_GATE);

    int cnt = g_cnt;
    int ci0 = blockIdx.x * 128;
    if (ci0 >= cnt) return;
    int nE = min(128, cnt - ci0);

    int tid = threadIdx.x;
    int wid = tid >> 5, lane = tid & 31;
    int wm = wid & 7, wn = wid >> 3;     // 8 x 2 warp grid
    int qr = lane >> 2, qc = lane & 3;   // quad row / quad col
    int r1 = 16 * wm + qr;               // warp rows r1, r1+8

    // indices + small constants
    if (tid < 128) {
        int e = (tid < nE) ? g_eidx[ci0 + tid] : g_eidx[ci0];
        sEg[tid] = e;
        sS[tid] = snd[e];
        sR[tid] = rcv[e];
        sB2[tid] = __ldg(b2 + tid);
        sWg[tid] = __ldg(wg + tid);
    } else if (tid < 384) {
        sB1[tid - 128] = __ldg(b1 + (tid - 128));
    }
    __syncthreads();

    // ---- gather A tile: [nf[s] | nf[r] | ef], tf32-rounded ----
    for (int i = tid; i < 128 * 40; i += 512) {
        int r = i / 40, q = i % 40;
        float4 v;
        int col;
        if (q < 16)      { v = __ldg((const float4*)(nf + (size_t)sS[r] * ND) + q);        col = 4 * q; }
        else if (q < 32) { v = __ldg((const float4*)(nf + (size_t)sR[r] * ND) + (q - 16)); col = 64 + 4 * (q - 16); }
        else             { v = __ldg((const float4*)(ef + (size_t)sEg[r] * ED) + (q - 32)); col = 128 + 4 * (q - 32); }
        v.x = tf32r(v.x); v.y = tf32r(v.y); v.z = tf32r(v.z); v.w = tf32r(v.w);
        *(float4*)&sA[r * SA_STR + col] = v;
    }
    __syncthreads();

    // ---- GEMM1: h(128x256) = relu(A(128x160) @ W1 + b1) ----
    float acc[16][4];                    // warp tile 16 rows x 128 cols
    #pragma unroll
    for (int nt = 0; nt < 16; nt++)
        #pragma unroll
        for (int j = 0; j < 4; j++) acc[nt][j] = 0.f;

    for (int kc = 0; kc < 5; kc++) {     // K=160, 32 per chunk
        __syncthreads();
        // stage chunk: sW[k][n] = tf32(W1[32kc+k][n]), n<256
        for (int j = tid; j < 2048; j += 512) {
            int k = j >> 6, n4 = j & 63;
            float4 v = __ldg((const float4*)(W1 + (size_t)(32 * kc + k) * HID) + n4);
            v.x = tf32r(v.x); v.y = tf32r(v.y); v.z = tf32r(v.z); v.w = tf32r(v.w);
            *(float4*)&sW[k * W1_STR + 4 * n4] = v;
        }
        __syncthreads();
        #pragma unroll
        for (int kb = 0; kb < 4; kb++) {
            int kg = 32 * kc + 8 * kb + qc;
            uint32_t a[4];
            a[0] = __float_as_uint(sA[r1 * SA_STR + kg]);
            a[1] = __float_as_uint(sA[(r1 + 8) * SA_STR + kg]);
            a[2] = __float_as_uint(sA[r1 * SA_STR + kg + 4]);
            a[3] = __float_as_uint(sA[(r1 + 8) * SA_STR + kg + 4]);
            int kin = 8 * kb + qc;
            #pragma unroll
            for (int nt = 0; nt < 16; nt++) {
                int nn = 128 * wn + 8 * nt + qr;
                uint32_t b[2];
                b[0] = __float_as_uint(sW[kin * W1_STR + nn]);
                b[1] = __float_as_uint(sW[(kin + 4) * W1_STR + nn]);
                mma168(acc[nt], a, b);
            }
        }
    }
    __syncthreads();                     // all GEMM1 reads of sA done before overwrite

    // epilogue1: h = tf32(relu(acc + b1)) -> sH
    #pragma unroll
    for (int nt = 0; nt < 16; nt++) {
        int c0 = 128 * wn + 8 * nt + 2 * qc;
        float bb0 = sB1[c0], bb1 = sB1[c0 + 1];
        float2 u;
        u.x = tf32r(fmaxf(acc[nt][0] + bb0, 0.f));
        u.y = tf32r(fmaxf(acc[nt][1] + bb1, 0.f));
        *(float2*)&sH[r1 * SH_STR + c0] = u;
        u.x = tf32r(fmaxf(acc[nt][2] + bb0, 0.f));
        u.y = tf32r(fmaxf(acc[nt][3] + bb1, 0.f));
        *(float2*)&sH[(r1 + 8) * SH_STR + c0] = u;
    }

    // ---- GEMM2: msg(128x128) = relu(h(128x256) @ W2 + b2) ----
    float acc2[8][4];                    // warp tile 16 rows x 64 cols
    #pragma unroll
    for (int nt = 0; nt < 8; nt++)
        #pragma unroll
        for (int j = 0; j < 4; j++) acc2[nt][j] = 0.f;

    for (int kc = 0; kc < 8; kc++) {     // K=256, 32 per chunk
        __syncthreads();                 // h writes / prev chunk reads complete
        for (int j = tid; j < 1024; j += 512) {
            int k = j >> 5, n4 = j & 31;
            float4 v = __ldg((const float4*)(W2 + (size_t)(32 * kc + k) * MSG) + n4);
            v.x = tf32r(v.x); v.y = tf32r(v.y); v.z = tf32r(v.z); v.w = tf32r(v.w);
            *(float4*)&sW[k * W2_STR + 4 * n4] = v;
        }
        __syncthreads();
        #pragma unroll
        for (int kb = 0; kb < 4; kb++) {
            int kg = 32 * kc + 8 * kb + qc;
            uint32_t a[4];
            a[0] = __float_as_uint(sH[r1 * SH_STR + kg]);
            a[1] = __float_as_uint(sH[(r1 + 8) * SH_STR + kg]);
            a[2] = __float_as_uint(sH[r1 * SH_STR + kg + 4]);
            a[3] = __float_as_uint(sH[(r1 + 8) * SH_STR + kg + 4]);
            int kin = 8 * kb + qc;
            #pragma unroll
            for (int nt = 0; nt < 8; nt++) {
                int nn = 64 * wn + 8 * nt + qr;
                uint32_t b[2];
                b[0] = __float_as_uint(sW[kin * W2_STR + nn]);
                b[1] = __float_as_uint(sW[(kin + 4) * W2_STR + nn]);
                mma168(acc2[nt], a, b);
            }
        }
    }

    // epilogue2: msg = relu(acc2 + b2); gate dot; store; logits
    {
        float gp1 = 0.f, gp2 = 0.f;
        int gr1 = ci0 + r1, gr2 = ci0 + r1 + 8;
        #pragma unroll
        for (int nt = 0; nt < 8; nt++) {
            int c0 = 64 * wn + 8 * nt + 2 * qc;
            float bb0 = sB2[c0], bb1 = sB2[c0 + 1];
            float w0 = sWg[c0], w1 = sWg[c0 + 1];
            float m0 = fmaxf(acc2[nt][0] + bb0, 0.f);
            float m1 = fmaxf(acc2[nt][1] + bb1, 0.f);
            float m2 = fmaxf(acc2[nt][2] + bb0, 0.f);
            float m3 = fmaxf(acc2[nt][3] + bb1, 0.f);
            gp1 += m0 * w0 + m1 * w1;
            gp2 += m2 * w0 + m3 * w1;
            if (r1 < nE)     *(float2*)&g_msg[(size_t)gr1 * MSG + c0] = make_float2(m0, m1);
            if (r1 + 8 < nE) *(float2*)&g_msg[(size_t)gr2 * MSG + c0] = make_float2(m2, m3);
        }
        gp1 += __shfl_xor_sync(0xffffffffu, gp1, 1);
        gp1 += __shfl_xor_sync(0xffffffffu, gp1, 2);
        gp2 += __shfl_xor_sync(0xffffffffu, gp2, 1);
        gp2 += __shfl_xor_sync(0xffffffffu, gp2, 2);
        if (qc == 0) {
            sGate[wn * 128 + r1] = gp1;
            sGate[wn * 128 + r1 + 8] = gp2;
        }
        __syncthreads();
        if (wn == 0 && qc == 0) {
            float bgv = __ldg(bg);
            #pragma unroll
            for (int rr = 0; rr < 2; rr++) {
                int r = r1 + 8 * rr;
                if (r < nE) {
                    float lgv = sGate[r] + sGate[128 + r] + bgv;
                    g_lg[ci0 + r] = lgv;
                    atomicMax(&g_segmax[sR[r]], f2ord(lgv));
                }
            }
        }
    }
}

// ---------------- softmax / aggregation ----------------
__global__ void k_softmax_e(const int* __restrict__ rcv) {
    int ci = blockIdx.x * blockDim.x + threadIdx.x;
    if (ci >= g_cnt) return;
    int e = g_eidx[ci];
    int r = rcv[e];
    float m = ord2f(g_segmax[r]);
    float ex = expf(g_lg[ci] - m);
    g_lg[ci] = ex;
    atomicAdd(&g_denom[r], ex);
}
__global__ void k_aggr(const int* __restrict__ rcv) {
    int idx = blockIdx.x * blockDim.x + threadIdx.x;
    int lane = idx & 31;
    int ci = idx >> 5;
    if (ci >= g_cnt) return;
    int e = g_eidx[ci];
    int r = rcv[e];
    float w = g_lg[ci] / (g_denom[r] + 1e-9f);
    float4 m = *(const float4*)&g_msg[(size_t)ci * MSG + lane * 4];
    float* dst = &g_aggr[(size_t)r * MSG + lane * 4];
    asm volatile("red.global.add.v4.f32 [%0], {%1,%2,%3,%4};"
                 :: "l"(dst), "f"(w * m.x), "f"(w * m.y), "f"(w * m.z), "f"(w * m.w)
                 : "memory");
}

// ---------------- agent MLP head (FFMA) ----------------
#define SMEM_AG (2 * 64 * HID * 4)
__global__ __launch_bounds__(256) void k_agent(
    const float* __restrict__ Wh1, const float* __restrict__ bh1,
    const float* __restrict__ Wh2, const float* __restrict__ bh2,
    const float* __restrict__ Wo,  const float* __restrict__ bo,
    float* __restrict__ out)
{
    extern __shared__ float smemf[];
    float* s1 = smemf;
    float* s2 = smemf + 64 * HID;

    int a0 = blockIdx.x * 64;
    int tid = threadIdx.x;
    int rg = tid >> 5, lane = tid & 31;
    int r0 = rg * 8;

    for (int j = tid; j < 64 * (MSG / 4); j += 256) {
        int r = j >> 5, c4 = j & 31;
        int a = a0 + r;
        float4 v = (a < N_AGENTS) ? *((const float4*)g_aggr + (size_t)a * (MSG / 4) + c4)
                                  : make_float4(0.f, 0.f, 0.f, 0.f);
        *(float4*)&s2[r * MSG + c4 * 4] = v;
    }
    __syncthreads();

    {
        int c0 = lane * 8;
        float acc[8][8];
        {
            float4 u0 = __ldg((const float4*)(bh1 + c0));
            float4 u1 = __ldg((const float4*)(bh1 + c0 + 4));
            float bv[8] = {u0.x,u0.y,u0.z,u0.w,u1.x,u1.y,u1.z,u1.w};
            #pragma unroll
            for (int i = 0; i < 8; i++)
                #pragma unroll
                for (int j = 0; j < 8; j++) acc[i][j] = bv[j];
        }
        for (int k4 = 0; k4 < MSG / 4; k4++) {
            float wv[4][8];
            #pragma unroll
            for (int kk = 0; kk < 4; kk++) {
                const float* wr = Wh1 + (k4 * 4 + kk) * HID + c0;
                float4 u0 = __ldg((const float4*)wr);
                float4 u1 = __ldg((const float4*)(wr + 4));
                wv[kk][0]=u0.x; wv[kk][1]=u0.y; wv[kk][2]=u0.z; wv[kk][3]=u0.w;
                wv[kk][4]=u1.x; wv[kk][5]=u1.y; wv[kk][6]=u1.z; wv[kk][7]=u1.w;
            }
            #pragma unroll
            for (int i = 0; i < 8; i++) {
                float4 a = *(float4*)&s2[(r0 + i) * MSG + k4 * 4];
                float av[4] = {a.x, a.y, a.z, a.w};
                #pragma unroll
                for (int kk = 0; kk < 4; kk++)
                    #pragma unroll
                    for (int j = 0; j < 8; j++) acc[i][j] += av[kk] * wv[kk][j];
            }
        }
        #pragma unroll
        for (int i = 0; i < 8; i++) {
            #pragma unroll
            for (int j = 0; j < 8; j++) acc[i][j] = fmaxf(acc[i][j], 0.f);
            *(float4*)&s1[(r0 + i) * HID + c0]     = make_float4(acc[i][0], acc[i][1], acc[i][2], acc[i][3]);
            *(float4*)&s1[(r0 + i) * HID + c0 + 4] = make_float4(acc[i][4], acc[i][5], acc[i][6], acc[i][7]);
        }
    }
    __syncthreads();

    {
        int c0 = lane * 8;
        float acc[8][8];
        {
            float4 u0 = __ldg((const float4*)(bh2 + c0));
            float4 u1 = __ldg((const float4*)(bh2 + c0 + 4));
            float bv[8] = {u0.x,u0.y,u0.z,u0.w,u1.x,u1.y,u1.z,u1.w};
            #pragma unroll
            for (int i = 0; i < 8; i++)
                #pragma unroll
                for (int j = 0; j < 8; j++) acc[i][j] = bv[j];
        }
        for (int k4 = 0; k4 < HID / 4; k4++) {
            float wv[4][8];
            #pragma unroll
            for (int kk = 0; kk < 4; kk++) {
                const float* wr = Wh2 + (k4 * 4 + kk) * HID + c0;
                float4 u0 = __ldg((const float4*)wr);
                float4 u1 = __ldg((const float4*)(wr + 4));
                wv[kk][0]=u0.x; wv[kk][1]=u0.y; wv[kk][2]=u0.z; wv[kk][3]=u0.w;
                wv[kk][4]=u1.x; wv[kk][5]=u1.y; wv[kk][6]=u1.z; wv[kk][7]=u1.w;
            }
            #pragma unroll
            for (int i = 0; i < 8; i++) {
                float4 a = *(float4*)&s1[(r0 + i) * HID + k4 * 4];
                float av[4] = {a.x, a.y, a.z, a.w};
                #pragma unroll
                for (int kk = 0; kk < 4; kk++)
                    #pragma unroll
                    for (int j = 0; j < 8; j++) acc[i][j] += av[kk] * wv[kk][j];
            }
        }
        __syncthreads();
        #pragma unroll
        for (int i = 0; i < 8; i++) {
            #pragma unroll
            for (int j = 0; j < 8; j++) acc[i][j] = fmaxf(acc[i][j], 0.f);
            *(float4*)&s2[(r0 + i) * HID + c0]     = make_float4(acc[i][0], acc[i][1], acc[i][2], acc[i][3]);
            *(float4*)&s2[(r0 + i) * HID + c0 + 4] = make_float4(acc[i][4], acc[i][5], acc[i][6], acc[i][7]);
        }
    }
    __syncthreads();

    {
        float wv[8];
        #pragma unroll
        for (int j = 0; j < 8; j++) wv[j] = __ldg(Wo + lane + 32 * j);
        float bov = __ldg(bo);
        #pragma unroll
        for (int i = 0; i < 8; i++) {
            int rw = r0 + i;
            float p = 0.f;
            #pragma unroll
            for (int j = 0; j < 8; j++) p += s2[rw * HID + lane + 32 * j] * wv[j];
            #pragma unroll
            for (int off = 16; off > 0; off >>= 1) p += __shfl_xor_sync(0xffffffffu, p, off);
            int a = a0 + rw;
            if (lane == 0 && a < N_AGENTS) out[a] = tanhf(p + bov);
        }
    }
}

// ---------------- launch ----------------
extern "C" void kernel_launch(void* const* d_in, const int* in_sizes, int n_in,
                              void* d_out, int out_size)
{
    const float* node = (const float*)d_in[0];
    const float* ef   = (const float*)d_in[1];
    const float* W1   = (const float*)d_in[2];
    const float* b1   = (const float*)d_in[3];
    const float* W2   = (const float*)d_in[4];
    const float* b2   = (const float*)d_in[5];
    const float* wg   = (const float*)d_in[6];
    const float* bg   = (const float*)d_in[7];
    const float* Wh1  = (const float*)d_in[8];
    const float* bh1  = (const float*)d_in[9];
    const float* Wh2  = (const float*)d_in[10];
    const float* bh2  = (const float*)d_in[11];
    const float* Wo   = (const float*)d_in[12];
    const float* bo   = (const float*)d_in[13];
    const int*   snd  = (const int*)d_in[14];
    const int*   rcv  = (const int*)d_in[15];
    float* out = (float*)d_out;

    cudaFuncSetAttribute(k_edge_mma, cudaFuncAttributeMaxDynamicSharedMemorySize, SMEM_EDGE);
    cudaFuncSetAttribute(k_agent,    cudaFuncAttributeMaxDynamicSharedMemorySize, SMEM_AG);

    k_init<<<12500, 256>>>();
    k_compact<<<(N_EDGESC + 255) / 256, 256>>>(rcv);
    k_edge_mma<<<(N_EDGESC + 127) / 128, 512, SMEM_EDGE>>>(node, ef, W1, b1, W2, b2, wg, bg, snd, rcv);
    k_softmax_e<<<(N_EDGESC + 255) / 256, 256>>>(rcv);
    k_aggr<<<(N_EDGESC * 32) / 256, 256>>>(rcv);
    k_agent<<<(N_AGENTS + 63) / 64, 256, SMEM_AG>>>(Wh1, bh1, Wh2, bh2, Wo, bo, out);
}

// round 6
// speedup vs baseline: 1.5622x; 1.0849x over previous
#include <cuda_runtime.h>
#include <math.h>
#include <stdint.h>

#define N_NODES  50000
#define N_EDGESC 800000
#define ND       64
#define ED       32
#define MSG      128
#define HID      256
#define N_AGENTS 25000

// ---------------- scratch ----------------
__device__ float        g_msg[(size_t)N_EDGESC * MSG];
__device__ float        g_lg[N_EDGESC];
__device__ int          g_eidx[N_EDGESC];
__device__ int          g_cnt;
__device__ unsigned int g_segmax[N_AGENTS];
__device__ float        g_denom[N_AGENTS];
__device__ float        g_aggr[(size_t)N_AGENTS * MSG];
// pre-swizzled tf32 "pair planes": slot s=4*(k>>3)+(k&3), comp=(k>>2)&1
// W1 plane: 80 slot-rows x 520 floats (260 float2, n<256 + pad)
__device__ __align__(16) float g_W1p[80 * 520];
// W2 plane: 128 slot-rows x 264 floats (132 float2, n<128 + pad)
__device__ __align__(16) float g_W2p[128 * 264];

__device__ __forceinline__ unsigned f2ord(float f) {
    unsigned u = __float_as_uint(f);
    return (u & 0x80000000u) ? ~u : (u | 0x80000000u);
}
__device__ __forceinline__ float ord2f(unsigned o) {
    unsigned u = (o & 0x80000000u) ? (o & 0x7fffffffu) : ~o;
    return __uint_as_float(u);
}
__device__ __forceinline__ float tf32r(float x) {
    uint32_t u;
    asm("cvt.rna.tf32.f32 %0, %1;" : "=r"(u) : "f"(x));
    return __uint_as_float(u);
}
__device__ __forceinline__ void mma168(float* d, const uint32_t* a, const uint32_t* b) {
    asm volatile(
        "mma.sync.aligned.m16n8k8.row.col.f32.tf32.tf32.f32 "
        "{%0,%1,%2,%3}, {%4,%5,%6,%7}, {%8,%9}, {%0,%1,%2,%3};"
        : "+f"(d[0]), "+f"(d[1]), "+f"(d[2]), "+f"(d[3])
        : "r"(a[0]), "r"(a[1]), "r"(a[2]), "r"(a[3]), "r"(b[0]), "r"(b[1]));
}
__device__ __forceinline__ void cp16(uint32_t dst, const void* src) {
    asm volatile("cp.async.cg.shared.global [%0], [%1], 16;" :: "r"(dst), "l"(src) : "memory");
}
#define CP_COMMIT() asm volatile("cp.async.commit_group;" ::: "memory")
#define CP_WAIT1()  asm volatile("cp.async.wait_group 1;" ::: "memory")

// ---------------- init / compact / prep ----------------
__global__ void k_init() {
    int i = blockIdx.x * blockDim.x + threadIdx.x;
    int stride = gridDim.x * blockDim.x;
    for (int j = i; j < N_AGENTS * MSG; j += stride) g_aggr[j] = 0.f;
    if (i < N_AGENTS) { g_segmax[i] = 0u; g_denom[i] = 0.f; }
    if (i == 0) g_cnt = 0;
}
__global__ void k_compact(const int* __restrict__ rcv) {
    int e = blockIdx.x * blockDim.x + threadIdx.x;
    if (e < N_EDGESC && rcv[e] < N_AGENTS) {
        int p = atomicAdd(&g_cnt, 1);
        g_eidx[p] = e;
    }
}
__global__ void k_prep(const float* __restrict__ W1, const float* __restrict__ W2) {
    int i = blockIdx.x * blockDim.x + threadIdx.x;
    if (i < 160 * 256) {                   // W1: [160][256] row-major
        int k = i >> 8, n = i & 255;
        int slot = 4 * (k >> 3) + (k & 3);
        int comp = (k >> 2) & 1;
        g_W1p[slot * 520 + 2 * n + comp] = tf32r(W1[(size_t)k * HID + n]);
    }
    int j = i - 160 * 256;
    if (j >= 0 && j < 256 * 128) {         // W2: [256][128] row-major
        int k = j >> 7, n = j & 127;
        int slot = 4 * (k >> 3) + (k & 3);
        int comp = (k >> 2) & 1;
        g_W2p[slot * 264 + 2 * n + comp] = tf32r(W2[(size_t)k * MSG + n]);
    }
}

// ---------------- fused edge MLP, pair-layout + cp.async pipeline ----------------
// smem offsets (bytes)
#define SA_STRF  164            // sA pair row stride (floats) = 82 float2
#define SH_STRF  260            // sH pair row stride (floats) = 130 float2
#define WBUF_STR 16640          // one W buffer (max chunk: 8 x 520 floats)
#define OFF_AH   0              // union sA(84K)/sH(133120)
#define OFF_WB   133120         // 3 x 16640 = 49920
#define OFF_EG   183040
#define OFF_S    183552
#define OFF_R    184064
#define OFF_B1   184576         // 256 f
#define OFF_B2   185600         // 128 f
#define OFF_WG   186112         // 128 f
#define OFF_GATE 186624         // 256 f
#define SMEM_EDGE 187648

__global__ __launch_bounds__(512, 1) void k_edge_mma(
    const float* __restrict__ nf, const float* __restrict__ ef,
    const float* __restrict__ b1, const float* __restrict__ b2,
    const float* __restrict__ wg, const float* __restrict__ bg,
    const int* __restrict__ snd, const int* __restrict__ rcv)
{
    extern __shared__ char smem[];
    uint32_t sb;
    asm("{ .reg .u64 t; cvta.to.shared.u64 t, %1; cvt.u32.u64 %0, t; }" : "=r"(sb) : "l"(smem));

    float* sAf = (float*)(smem + OFF_AH);
    int*   sEg = (int*)(smem + OFF_EG);
    int*   sS  = (int*)(smem + OFF_S);
    int*   sR  = (int*)(smem + OFF_R);
    float* sB1 = (float*)(smem + OFF_B1);
    float* sB2 = (float*)(smem + OFF_B2);
    float* sWg = (float*)(smem + OFF_WG);
    float* sGate = (float*)(smem + OFF_GATE);

    int cnt = g_cnt;
    int ci0 = blockIdx.x * 128;
    if (ci0 >= cnt) return;
    int nE = min(128, cnt - ci0);

    int tid = threadIdx.x;
    int wid = tid >> 5, lane = tid & 31;
    int wm = wid & 7, wn = wid >> 3;       // 8 x 2 warp grid
    int qr = lane >> 2, qc = lane & 3;
    int r1 = 16 * wm + qr;

    // prime W1 chunk0 -> buf0
    {
        const float4* src = (const float4*)g_W1p;
        uint32_t dst = sb + OFF_WB;
        for (int j = tid; j < 1040; j += 512) cp16(dst + j * 16, src + j);
        CP_COMMIT();
    }

    // indices + consts
    if (tid < 128) {
        int e = (tid < nE) ? g_eidx[ci0 + tid] : g_eidx[ci0];
        sEg[tid] = e;
        sS[tid] = snd[e];
        sR[tid] = rcv[e];
        sB2[tid] = __ldg(b2 + tid);
        sWg[tid] = __ldg(wg + tid);
    } else if (tid < 384) {
        sB1[tid - 128] = __ldg(b1 + (tid - 128));
    }
    __syncthreads();

    // gather A tile [nf[s]|nf[r]|ef] into pair layout
    for (int i = tid; i < 128 * 40; i += 512) {
        int r = i / 40, q = i % 40;
        float4 v;
        int cb;
        if (q < 16)      { v = __ldg((const float4*)(nf + (size_t)sS[r] * ND) + q);         cb = 4 * q; }
        else if (q < 32) { v = __ldg((const float4*)(nf + (size_t)sR[r] * ND) + (q - 16));  cb = 64 + 4 * (q - 16); }
        else             { v = __ldg((const float4*)(ef + (size_t)sEg[r] * ED) + (q - 32)); cb = 128 + 4 * (q - 32); }
        int g = cb >> 3, comp = (cb >> 2) & 1;
        float* p = sAf + r * SA_STRF + 8 * g + comp;
        p[0] = tf32r(v.x); p[2] = tf32r(v.y); p[4] = tf32r(v.z); p[6] = tf32r(v.w);
    }

    // ---- GEMM1: 128x256, K=160, 10 chunks of 16k ----
    float acc[16][4];
    #pragma unroll
    for (int nt = 0; nt < 16; nt++)
        #pragma unroll
        for (int j = 0; j < 4; j++) acc[nt][j] = 0.f;

    const float2* sAp = (const float2*)sAf;
    for (int kc = 0; kc < 10; kc++) {
        if (kc + 1 < 10) {
            const float4* src = (const float4*)g_W1p + (size_t)(kc + 1) * 1040;
            uint32_t dst = sb + OFF_WB + ((kc + 1) % 3) * WBUF_STR;
            for (int j = tid; j < 1040; j += 512) cp16(dst + j * 16, src + j);
        }
        CP_COMMIT();
        CP_WAIT1();
        __syncthreads();
        const float2* wb = (const float2*)(smem + OFF_WB + (kc % 3) * WBUF_STR);
        #pragma unroll
        for (int kbl = 0; kbl < 2; kbl++) {
            int slotg = 8 * kc + 4 * kbl + qc;
            float2 a0 = sAp[r1 * 82 + slotg];
            float2 a1 = sAp[(r1 + 8) * 82 + slotg];
            uint32_t af[4] = {__float_as_uint(a0.x), __float_as_uint(a1.x),
                              __float_as_uint(a0.y), __float_as_uint(a1.y)};
            int srow = 4 * kbl + qc;
            #pragma unroll
            for (int nt = 0; nt < 16; nt++) {
                int nn = 128 * wn + 8 * nt + qr;
                float2 bv = wb[srow * 260 + nn];
                uint32_t bf[2] = {__float_as_uint(bv.x), __float_as_uint(bv.y)};
                mma168(acc[nt], af, bf);
            }
        }
    }
    __syncthreads();   // all GEMM1 reads of sA / W bufs done

    // prime W2 chunk0 -> buf0
    {
        const float4* src = (const float4*)g_W2p;
        uint32_t dst = sb + OFF_WB;
        for (int j = tid; j < 528; j += 512) cp16(dst + j * 16, src + j);
        CP_COMMIT();
    }

    // epilogue1: h = tf32(relu(acc + b1)) -> sH pair layout (overwrites sA region)
    float* sHf = sAf;
    #pragma unroll
    for (int nt = 0; nt < 16; nt++) {
        int c0 = 128 * wn + 8 * nt + 2 * qc;
        int gg = 16 * wn + nt;
        int slotb = 4 * gg + 2 * (qc & 1);
        int comp = qc >> 1;
        float bb0 = sB1[c0], bb1 = sB1[c0 + 1];
        float* p0 = sHf + r1 * SH_STRF + 2 * slotb + comp;
        p0[0] = tf32r(fmaxf(acc[nt][0] + bb0, 0.f));
        p0[2] = tf32r(fmaxf(acc[nt][1] + bb1, 0.f));
        float* p1 = sHf + (r1 + 8) * SH_STRF + 2 * slotb + comp;
        p1[0] = tf32r(fmaxf(acc[nt][2] + bb0, 0.f));
        p1[2] = tf32r(fmaxf(acc[nt][3] + bb1, 0.f));
    }

    // ---- GEMM2: 128x128, K=256, 16 chunks of 16k ----
    float acc2[8][4];
    #pragma unroll
    for (int nt = 0; nt < 8; nt++)
        #pragma unroll
        for (int j = 0; j < 4; j++) acc2[nt][j] = 0.f;

    const float2* sHp = (const float2*)sHf;
    for (int kc = 0; kc < 16; kc++) {
        if (kc + 1 < 16) {
            const float4* src = (const float4*)g_W2p + (size_t)(kc + 1) * 528;
            uint32_t dst = sb + OFF_WB + ((kc + 1) % 3) * WBUF_STR;
            for (int j = tid; j < 528; j += 512) cp16(dst + j * 16, src + j);
        }
        CP_COMMIT();
        CP_WAIT1();
        __syncthreads();
        const float2* wb = (const float2*)(smem + OFF_WB + (kc % 3) * WBUF_STR);
        #pragma unroll
        for (int kbl = 0; kbl < 2; kbl++) {
            int slotg = 8 * kc + 4 * kbl + qc;
            float2 a0 = sHp[r1 * 130 + slotg];
            float2 a1 = sHp[(r1 + 8) * 130 + slotg];
            uint32_t af[4] = {__float_as_uint(a0.x), __float_as_uint(a1.x),
                              __float_as_uint(a0.y), __float_as_uint(a1.y)};
            int srow = 4 * kbl + qc;
            #pragma unroll
            for (int nt = 0; nt < 8; nt++) {
                int nn = 64 * wn + 8 * nt + qr;
                float2 bv = wb[srow * 132 + nn];
                uint32_t bf[2] = {__float_as_uint(bv.x), __float_as_uint(bv.y)};
                mma168(acc2[nt], af, bf);
            }
        }
    }

    // epilogue2: msg = relu(acc2 + b2); gate dot; segmax; store
    {
        float gp1 = 0.f, gp2 = 0.f;
        int gr1 = ci0 + r1, gr2 = ci0 + r1 + 8;
        #pragma unroll
        for (int nt = 0; nt < 8; nt++) {
            int c0 = 64 * wn + 8 * nt + 2 * qc;
            float bb0 = sB2[c0], bb1 = sB2[c0 + 1];
            float w0 = sWg[c0], w1 = sWg[c0 + 1];
            float m0 = fmaxf(acc2[nt][0] + bb0, 0.f);
            float m1 = fmaxf(acc2[nt][1] + bb1, 0.f);
            float m2 = fmaxf(acc2[nt][2] + bb0, 0.f);
            float m3 = fmaxf(acc2[nt][3] + bb1, 0.f);
            gp1 += m0 * w0 + m1 * w1;
            gp2 += m2 * w0 + m3 * w1;
            if (r1 < nE)     *(float2*)&g_msg[(size_t)gr1 * MSG + c0] = make_float2(m0, m1);
            if (r1 + 8 < nE) *(float2*)&g_msg[(size_t)gr2 * MSG + c0] = make_float2(m2, m3);
        }
        gp1 += __shfl_xor_sync(0xffffffffu, gp1, 1);
        gp1 += __shfl_xor_sync(0xffffffffu, gp1, 2);
        gp2 += __shfl_xor_sync(0xffffffffu, gp2, 1);
        gp2 += __shfl_xor_sync(0xffffffffu, gp2, 2);
        if (qc == 0) {
            sGate[wn * 128 + r1] = gp1;
            sGate[wn * 128 + r1 + 8] = gp2;
        }
        __syncthreads();
        if (wn == 0 && qc == 0) {
            float bgv = __ldg(bg);
            #pragma unroll
            for (int rr = 0; rr < 2; rr++) {
                int r = r1 + 8 * rr;
                if (r < nE) {
                    float lgv = sGate[r] + sGate[128 + r] + bgv;
                    g_lg[ci0 + r] = lgv;
                    atomicMax(&g_segmax[sR[r]], f2ord(lgv));
                }
            }
        }
    }
}

// ---------------- fused exp + denom + weighted scatter ----------------
__global__ void k_aggr(const int* __restrict__ rcv) {
    int idx = blockIdx.x * blockDim.x + threadIdx.x;
    int lane = idx & 31;
    int ci = idx >> 5;
    if (ci >= g_cnt) return;
    int e = g_eidx[ci];
    int r = rcv[e];
    float ex = expf(g_lg[ci] - ord2f(g_segmax[r]));
    if (lane == 0) atomicAdd(&g_denom[r], ex);
    float4 m = *(const float4*)&g_msg[(size_t)ci * MSG + lane * 4];
    float* dst = &g_aggr[(size_t)r * MSG + lane * 4];
    asm volatile("red.global.add.v4.f32 [%0], {%1,%2,%3,%4};"
                 :: "l"(dst), "f"(ex * m.x), "f"(ex * m.y), "f"(ex * m.z), "f"(ex * m.w)
                 : "memory");
}

// ---------------- agent MLP head (FFMA fp32, fused divide) ----------------
#define SMEM_AG (2 * 64 * HID * 4)
__global__ __launch_bounds__(256) void k_agent(
    const float* __restrict__ Wh1, const float* __restrict__ bh1,
    const float* __restrict__ Wh2, const float* __restrict__ bh2,
    const float* __restrict__ Wo,  const float* __restrict__ bo,
    float* __restrict__ out)
{
    extern __shared__ float smemf[];
    float* s1 = smemf;
    float* s2 = smemf + 64 * HID;
    __shared__ float sInv[64];

    int a0 = blockIdx.x * 64;
    int tid = threadIdx.x;
    int rg = tid >> 5, lane = tid & 31;
    int r0 = rg * 8;

    if (tid < 64) {
        int a = a0 + tid;
        sInv[tid] = (a < N_AGENTS) ? 1.f / (g_denom[a] + 1e-9f) : 0.f;
    }
    __syncthreads();

    for (int j = tid; j < 64 * (MSG / 4); j += 256) {
        int r = j >> 5, c4 = j & 31;
        int a = a0 + r;
        float4 v = (a < N_AGENTS) ? *((const float4*)g_aggr + (size_t)a * (MSG / 4) + c4)
                                  : make_float4(0.f, 0.f, 0.f, 0.f);
        float inv = sInv[r];
        *(float4*)&s2[r * MSG + c4 * 4] = make_float4(v.x * inv, v.y * inv, v.z * inv, v.w * inv);
    }
    __syncthreads();

    {
        int c0 = lane * 8;
        float acc[8][8];
        {
            float4 u0 = __ldg((const float4*)(bh1 + c0));
            float4 u1 = __ldg((const float4*)(bh1 + c0 + 4));
            float bv[8] = {u0.x,u0.y,u0.z,u0.w,u1.x,u1.y,u1.z,u1.w};
            #pragma unroll
            for (int i = 0; i < 8; i++)
                #pragma unroll
                for (int j = 0; j < 8; j++) acc[i][j] = bv[j];
        }
        for (int k4 = 0; k4 < MSG / 4; k4++) {
            float wv[4][8];
            #pragma unroll
            for (int kk = 0; kk < 4; kk++) {
                const float* wr = Wh1 + (k4 * 4 + kk) * HID + c0;
                float4 u0 = __ldg((const float4*)wr);
                float4 u1 = __ldg((const float4*)(wr + 4));
                wv[kk][0]=u0.x; wv[kk][1]=u0.y; wv[kk][2]=u0.z; wv[kk][3]=u0.w;
                wv[kk][4]=u1.x; wv[kk][5]=u1.y; wv[kk][6]=u1.z; wv[kk][7]=u1.w;
            }
            #pragma unroll
            for (int i = 0; i < 8; i++) {
                float4 a = *(float4*)&s2[(r0 + i) * MSG + k4 * 4];
                float av[4] = {a.x, a.y, a.z, a.w};
                #pragma unroll
                for (int kk = 0; kk < 4; kk++)
                    #pragma unroll
                    for (int j = 0; j < 8; j++) acc[i][j] += av[kk] * wv[kk][j];
            }
        }
        #pragma unroll
        for (int i = 0; i < 8; i++) {
            #pragma unroll
            for (int j = 0; j < 8; j++) acc[i][j] = fmaxf(acc[i][j], 0.f);
            *(float4*)&s1[(r0 + i) * HID + c0]     = make_float4(acc[i][0], acc[i][1], acc[i][2], acc[i][3]);
            *(float4*)&s1[(r0 + i) * HID + c0 + 4] = make_float4(acc[i][4], acc[i][5], acc[i][6], acc[i][7]);
        }
    }
    __syncthreads();

    {
        int c0 = lane * 8;
        float acc[8][8];
        {
            float4 u0 = __ldg((const float4*)(bh2 + c0));
            float4 u1 = __ldg((const float4*)(bh2 + c0 + 4));
            float bv[8] = {u0.x,u0.y,u0.z,u0.w,u1.x,u1.y,u1.z,u1.w};
            #pragma unroll
            for (int i = 0; i < 8; i++)
                #pragma unroll
                for (int j = 0; j < 8; j++) acc[i][j] = bv[j];
        }
        for (int k4 = 0; k4 < HID / 4; k4++) {
            float wv[4][8];
            #pragma unroll
            for (int kk = 0; kk < 4; kk++) {
                const float* wr = Wh2 + (k4 * 4 + kk) * HID + c0;
                float4 u0 = __ldg((const float4*)wr);
                float4 u1 = __ldg((const float4*)(wr + 4));
                wv[kk][0]=u0.x; wv[kk][1]=u0.y; wv[kk][2]=u0.z; wv[kk][3]=u0.w;
                wv[kk][4]=u1.x; wv[kk][5]=u1.y; wv[kk][6]=u1.z; wv[kk][7]=u1.w;
            }
            #pragma unroll
            for (int i = 0; i < 8; i++) {
                float4 a = *(float4*)&s1[(r0 + i) * HID + k4 * 4];
                float av[4] = {a.x, a.y, a.z, a.w};
                #pragma unroll
                for (int kk = 0; kk < 4; kk++)
                    #pragma unroll
                    for (int j = 0; j < 8; j++) acc[i][j] += av[kk] * wv[kk][j];
            }
        }
        __syncthreads();
        #pragma unroll
        for (int i = 0; i < 8; i++) {
            #pragma unroll
            for (int j = 0; j < 8; j++) acc[i][j] = fmaxf(acc[i][j], 0.f);
            *(float4*)&s2[(r0 + i) * HID + c0]     = make_float4(acc[i][0], acc[i][1], acc[i][2], acc[i][3]);
            *(float4*)&s2[(r0 + i) * HID + c0 + 4] = make_float4(acc[i][4], acc[i][5], acc[i][6], acc[i][7]);
        }
    }
    __syncthreads();

    {
        float wv[8];
        #pragma unroll
        for (int j = 0; j < 8; j++) wv[j] = __ldg(Wo + lane + 32 * j);
        float bov = __ldg(bo);
        #pragma unroll
        for (int i = 0; i < 8; i++) {
            int rw = r0 + i;
            float p = 0.f;
            #pragma unroll
            for (int j = 0; j < 8; j++) p += s2[rw * HID + lane + 32 * j] * wv[j];
            #pragma unroll
            for (int off = 16; off > 0; off >>= 1) p += __shfl_xor_sync(0xffffffffu, p, off);
            int a = a0 + rw;
            if (lane == 0 && a < N_AGENTS) out[a] = tanhf(p + bov);
        }
    }
}

// ---------------- launch ----------------
extern "C" void kernel_launch(void* const* d_in, const int* in_sizes, int n_in,
                              void* d_out, int out_size)
{
    const float* node = (const float*)d_in[0];
    const float* ef   = (const float*)d_in[1];
    const float* W1   = (const float*)d_in[2];
    const float* b1   = (const float*)d_in[3];
    const float* W2   = (const float*)d_in[4];
    const float* b2   = (const float*)d_in[5];
    const float* wg   = (const float*)d_in[6];
    const float* bg   = (const float*)d_in[7];
    const float* Wh1  = (const float*)d_in[8];
    const float* bh1  = (const float*)d_in[9];
    const float* Wh2  = (const float*)d_in[10];
    const float* bh2  = (const float*)d_in[11];
    const float* Wo   = (const float*)d_in[12];
    const float* bo   = (const float*)d_in[13];
    const int*   snd  = (const int*)d_in[14];
    const int*   rcv  = (const int*)d_in[15];
    float* out = (float*)d_out;

    cudaFuncSetAttribute(k_edge_mma, cudaFuncAttributeMaxDynamicSharedMemorySize, SMEM_EDGE);
    cudaFuncSetAttribute(k_agent,    cudaFuncAttributeMaxDynamicSharedMemorySize, SMEM_AG);

    k_init<<<12500, 256>>>();
    k_compact<<<(N_EDGESC + 255) / 256, 256>>>(rcv);
    k_prep<<<(160 * 256 + 256 * 128 + 255) / 256, 256>>>(W1, W2);
    k_edge_mma<<<(N_EDGESC + 127) / 128, 512, SMEM_EDGE>>>(node, ef, b1, b2, wg, bg, snd, rcv);
    k_aggr<<<(N_EDGESC * 32) / 256, 256>>>(rcv);
    k_agent<<<(N_AGENTS + 63) / 64, 256, SMEM_AG>>>(Wh1, bh1, Wh2, bh2, Wo, bo, out);
}

// round 7
// speedup vs baseline: 1.6203x; 1.0372x over previous
#include <cuda_runtime.h>
#include <math.h>
#include <stdint.h>

#define N_NODES  50000
#define N_EDGESC 800000
#define ND       64
#define ED       32
#define MSG      128
#define HID      256
#define N_AGENTS 25000

// ---------------- scratch ----------------
__device__ float        g_msg[(size_t)N_EDGESC * MSG];
__device__ float        g_lg[N_EDGESC];
__device__ int          g_eidx[N_EDGESC];
__device__ int          g_cnt;
__device__ unsigned int g_segmax[N_AGENTS];
__device__ float        g_denom[N_AGENTS];
__device__ float        g_aggr[(size_t)N_AGENTS * MSG];
// pre-swizzled tf32 "pair planes": slot s=4*(k>>3)+(k&3), comp=(k>>2)&1
__device__ __align__(16) float g_W1p[80 * 520];    // 260 float2 (n<256) per slot-row
__device__ __align__(16) float g_W2p[128 * 264];   // 132 float2 (n<128) per slot-row

__device__ __forceinline__ unsigned f2ord(float f) {
    unsigned u = __float_as_uint(f);
    return (u & 0x80000000u) ? ~u : (u | 0x80000000u);
}
__device__ __forceinline__ float ord2f(unsigned o) {
    unsigned u = (o & 0x80000000u) ? (o & 0x7fffffffu) : ~o;
    return __uint_as_float(u);
}
__device__ __forceinline__ float tf32r(float x) {
    uint32_t u;
    asm("cvt.rna.tf32.f32 %0, %1;" : "=r"(u) : "f"(x));
    return __uint_as_float(u);
}
__device__ __forceinline__ void mma168(float* d, const uint32_t* a, const uint32_t* b) {
    asm volatile(
        "mma.sync.aligned.m16n8k8.row.col.f32.tf32.tf32.f32 "
        "{%0,%1,%2,%3}, {%4,%5,%6,%7}, {%8,%9}, {%0,%1,%2,%3};"
        : "+f"(d[0]), "+f"(d[1]), "+f"(d[2]), "+f"(d[3])
        : "r"(a[0]), "r"(a[1]), "r"(a[2]), "r"(a[3]), "r"(b[0]), "r"(b[1]));
}
__device__ __forceinline__ void cp16(uint32_t dst, const void* src) {
    asm volatile("cp.async.cg.shared.global [%0], [%1], 16;" :: "r"(dst), "l"(src) : "memory");
}
#define CP_COMMIT() asm volatile("cp.async.commit_group;" ::: "memory")
#define CP_WAIT1()  asm volatile("cp.async.wait_group 1;" ::: "memory")

// ---------------- init / compact / prep ----------------
__global__ void k_init() {
    int i = blockIdx.x * blockDim.x + threadIdx.x;
    int stride = gridDim.x * blockDim.x;
    for (int j = i; j < N_AGENTS * MSG; j += stride) g_aggr[j] = 0.f;
    if (i < N_AGENTS) { g_segmax[i] = 0u; g_denom[i] = 0.f; }
    if (i == 0) g_cnt = 0;
}
__global__ void k_compact(const int* __restrict__ rcv) {
    int e = blockIdx.x * blockDim.x + threadIdx.x;
    if (e < N_EDGESC && rcv[e] < N_AGENTS) {
        int p = atomicAdd(&g_cnt, 1);
        g_eidx[p] = e;
    }
}
__global__ void k_prep(const float* __restrict__ W1, const float* __restrict__ W2) {
    int i = blockIdx.x * blockDim.x + threadIdx.x;
    if (i < 160 * 256) {
        int k = i >> 8, n = i & 255;
        int slot = 4 * (k >> 3) + (k & 3);
        int comp = (k >> 2) & 1;
        g_W1p[slot * 520 + 2 * n + comp] = tf32r(W1[(size_t)k * HID + n]);
    }
    int j = i - 160 * 256;
    if (j >= 0 && j < 256 * 128) {
        int k = j >> 7, n = j & 127;
        int slot = 4 * (k >> 3) + (k & 3);
        int comp = (k >> 2) & 1;
        g_W2p[slot * 264 + 2 * n + comp] = tf32r(W2[(size_t)k * MSG + n]);
    }
}

// ---------------- fused edge MLP ----------------
// pair strides chosen so row-stride bytes mod 128 == 32 (conflict-free A-frag lds.64)
#define SA_STR2  84             // sA pair row stride (float2); 168 floats, 672 B
#define SH_STR2  132            // sH pair row stride (float2); 264 floats, 1056 B
#define WBUF_STR 16640
#define OFF_AH   0              // union: sA 86016 / sH 135168
#define OFF_WB   135168         // 3 x 16640
#define OFF_EG   185088
#define OFF_S    185600
#define OFF_R    186112
#define OFF_B1   186624
#define OFF_B2   187648
#define OFF_WG   188160
#define OFF_GATE 188672         // 4 x 128 floats
#define SMEM_EDGE 190720

__global__ __launch_bounds__(512, 1) void k_edge_mma(
    const float* __restrict__ nf, const float* __restrict__ ef,
    const float* __restrict__ b1, const float* __restrict__ b2,
    const float* __restrict__ wg, const float* __restrict__ bg,
    const int* __restrict__ snd, const int* __restrict__ rcv)
{
    extern __shared__ char smem[];
    uint32_t sb;
    asm("{ .reg .u64 t; cvta.to.shared.u64 t, %1; cvt.u32.u64 %0, t; }" : "=r"(sb) : "l"(smem));

    float* sAf = (float*)(smem + OFF_AH);
    int*   sEg = (int*)(smem + OFF_EG);
    int*   sS  = (int*)(smem + OFF_S);
    int*   sR  = (int*)(smem + OFF_R);
    float* sB1 = (float*)(smem + OFF_B1);
    float* sB2 = (float*)(smem + OFF_B2);
    float* sWg = (float*)(smem + OFF_WG);
    float* sGate = (float*)(smem + OFF_GATE);

    int cnt = g_cnt;
    int ci0 = blockIdx.x * 128;
    if (ci0 >= cnt) return;
    int nE = min(128, cnt - ci0);

    int tid = threadIdx.x;
    int wid = tid >> 5, lane = tid & 31;
    int qr = lane >> 2, qc = lane & 3;

    // prime W1 chunk0 -> buf0
    {
        const float4* src = (const float4*)g_W1p;
        uint32_t dst = sb + OFF_WB;
        for (int j = tid; j < 1040; j += 512) cp16(dst + j * 16, src + j);
        CP_COMMIT();
    }

    if (tid < 128) {
        int e = (tid < nE) ? g_eidx[ci0 + tid] : g_eidx[ci0];
        sEg[tid] = e;
        sS[tid] = snd[e];
        sR[tid] = rcv[e];
        sB2[tid] = __ldg(b2 + tid);
        sWg[tid] = __ldg(wg + tid);
    } else if (tid < 384) {
        sB1[tid - 128] = __ldg(b1 + (tid - 128));
    }
    __syncthreads();

    // gather A tile [nf[s]|nf[r]|ef] into pair layout
    for (int i = tid; i < 128 * 40; i += 512) {
        int r = i / 40, q = i % 40;
        float4 v;
        int cb;
        if (q < 16)      { v = __ldg((const float4*)(nf + (size_t)sS[r] * ND) + q);         cb = 4 * q; }
        else if (q < 32) { v = __ldg((const float4*)(nf + (size_t)sR[r] * ND) + (q - 16));  cb = 64 + 4 * (q - 16); }
        else             { v = __ldg((const float4*)(ef + (size_t)sEg[r] * ED) + (q - 32)); cb = 128 + 4 * (q - 32); }
        int g = cb >> 3, comp = (cb >> 2) & 1;
        float* p = sAf + r * (2 * SA_STR2) + 8 * g + comp;
        p[0] = tf32r(v.x); p[2] = tf32r(v.y); p[4] = tf32r(v.z); p[6] = tf32r(v.w);
    }

    // ---- GEMM1: 128x256, K=160. Warp grid 2x8: Mw=64, Nw=32 ----
    int wm1 = wid & 1, wn1 = wid >> 1;
    int rb1 = 64 * wm1, cb1 = 32 * wn1;

    float acc1[4][4][4];
    #pragma unroll
    for (int mt = 0; mt < 4; mt++)
        #pragma unroll
        for (int nt = 0; nt < 4; nt++)
            #pragma unroll
            for (int j = 0; j < 4; j++) acc1[mt][nt][j] = 0.f;

    const float2* sAp = (const float2*)sAf;
    for (int kc = 0; kc < 10; kc++) {
        if (kc + 1 < 10) {
            const float4* src = (const float4*)g_W1p + (size_t)(kc + 1) * 1040;
            uint32_t dst = sb + OFF_WB + ((kc + 1) % 3) * WBUF_STR;
            for (int j = tid; j < 1040; j += 512) cp16(dst + j * 16, src + j);
        }
        CP_COMMIT();
        CP_WAIT1();
        __syncthreads();
        const float2* wb = (const float2*)(smem + OFF_WB + (kc % 3) * WBUF_STR);
        #pragma unroll
        for (int kbl = 0; kbl < 2; kbl++) {
            int G = 2 * kc + kbl;
            int aslot = 4 * G + qc;
            uint32_t af[4][4];
            #pragma unroll
            for (int mt = 0; mt < 4; mt++) {
                float2 a0 = sAp[(rb1 + 16 * mt + qr) * SA_STR2 + aslot];
                float2 a1 = sAp[(rb1 + 16 * mt + 8 + qr) * SA_STR2 + aslot];
                af[mt][0] = __float_as_uint(a0.x); af[mt][1] = __float_as_uint(a1.x);
                af[mt][2] = __float_as_uint(a0.y); af[mt][3] = __float_as_uint(a1.y);
            }
            int srow = 4 * kbl + qc;
            uint32_t bf[4][2];
            #pragma unroll
            for (int nt = 0; nt < 4; nt++) {
                float2 bv = wb[srow * 260 + cb1 + 8 * nt + qr];
                bf[nt][0] = __float_as_uint(bv.x); bf[nt][1] = __float_as_uint(bv.y);
            }
            #pragma unroll
            for (int mt = 0; mt < 4; mt++)
                #pragma unroll
                for (int nt = 0; nt < 4; nt++)
                    mma168(acc1[mt][nt], af[mt], bf[nt]);
        }
    }
    __syncthreads();   // all GEMM1 reads of sA / W bufs done before sH overwrite

    // prime W2 chunk0 -> buf0
    {
        const float4* src = (const float4*)g_W2p;
        uint32_t dst = sb + OFF_WB;
        for (int j = tid; j < 528; j += 512) cp16(dst + j * 16, src + j);
        CP_COMMIT();
    }

    // epilogue1: h = tf32(relu(acc + b1)) -> sH pair layout
    float* sHf = sAf;
    #pragma unroll
    for (int mt = 0; mt < 4; mt++) {
        int ra = rb1 + 16 * mt + qr, rbr = ra + 8;
        #pragma unroll
        for (int nt = 0; nt < 4; nt++) {
            int c0 = cb1 + 8 * nt + 2 * qc;
            float bb0 = sB1[c0], bb1 = sB1[c0 + 1];
            float* d = acc1[mt][nt];
            #pragma unroll
            for (int u = 0; u < 2; u++) {
                int c = c0 + u;
                int g = c >> 3, e = c & 7;
                int idx = 8 * g + 2 * (e & 3) + (e >> 2);
                sHf[ra * (2 * SH_STR2) + idx]  = tf32r(fmaxf(d[u] + (u ? bb1 : bb0), 0.f));
                sHf[rbr * (2 * SH_STR2) + idx] = tf32r(fmaxf(d[2 + u] + (u ? bb1 : bb0), 0.f));
            }
        }
    }

    // ---- GEMM2: 128x128, K=256. Warp grid 4x4: Mw=32, Nw=32 ----
    int wm2 = wid & 3, wn2 = wid >> 2;
    int rb2 = 32 * wm2, cb2 = 32 * wn2;

    float acc2[2][4][4];
    #pragma unroll
    for (int mt = 0; mt < 2; mt++)
        #pragma unroll
        for (int nt = 0; nt < 4; nt++)
            #pragma unroll
            for (int j = 0; j < 4; j++) acc2[mt][nt][j] = 0.f;

    const float2* sHp = (const float2*)sHf;
    for (int kc = 0; kc < 16; kc++) {
        if (kc + 1 < 16) {
            const float4* src = (const float4*)g_W2p + (size_t)(kc + 1) * 528;
            uint32_t dst = sb + OFF_WB + ((kc + 1) % 3) * WBUF_STR;
            for (int j = tid; j < 528; j += 512) cp16(dst + j * 16, src + j);
        }
        CP_COMMIT();
        CP_WAIT1();
        __syncthreads();
        const float2* wb = (const float2*)(smem + OFF_WB + (kc % 3) * WBUF_STR);
        #pragma unroll
        for (int kbl = 0; kbl < 2; kbl++) {
            int G = 2 * kc + kbl;
            int aslot = 4 * G + qc;
            uint32_t af[2][4];
            #pragma unroll
            for (int mt = 0; mt < 2; mt++) {
                float2 a0 = sHp[(rb2 + 16 * mt + qr) * SH_STR2 + aslot];
                float2 a1 = sHp[(rb2 + 16 * mt + 8 + qr) * SH_STR2 + aslot];
                af[mt][0] = __float_as_uint(a0.x); af[mt][1] = __float_as_uint(a1.x);
                af[mt][2] = __float_as_uint(a0.y); af[mt][3] = __float_as_uint(a1.y);
            }
            int srow = 4 * kbl + qc;
            uint32_t bf[4][2];
            #pragma unroll
            for (int nt = 0; nt < 4; nt++) {
                float2 bv = wb[srow * 132 + cb2 + 8 * nt + qr];
                bf[nt][0] = __float_as_uint(bv.x); bf[nt][1] = __float_as_uint(bv.y);
            }
            #pragma unroll
            for (int mt = 0; mt < 2; mt++)
                #pragma unroll
                for (int nt = 0; nt < 4; nt++)
                    mma168(acc2[mt][nt], af[mt], bf[nt]);
        }
    }

    // epilogue2: msg = relu(acc2 + b2); gate partials; store
    {
        float gpa[2] = {0.f, 0.f}, gpb[2] = {0.f, 0.f};
        #pragma unroll
        for (int mt = 0; mt < 2; mt++) {
            int ra = rb2 + 16 * mt + qr, rbr = ra + 8;
            #pragma unroll
            for (int nt = 0; nt < 4; nt++) {
                int c0 = cb2 + 8 * nt + 2 * qc;
                float bb0 = sB2[c0], bb1 = sB2[c0 + 1];
                float w0 = sWg[c0], w1 = sWg[c0 + 1];
                float* d = acc2[mt][nt];
                float m0 = fmaxf(d[0] + bb0, 0.f);
                float m1 = fmaxf(d[1] + bb1, 0.f);
                float m2 = fmaxf(d[2] + bb0, 0.f);
                float m3 = fmaxf(d[3] + bb1, 0.f);
                gpa[mt] += m0 * w0 + m1 * w1;
                gpb[mt] += m2 * w0 + m3 * w1;
                if (ra < nE)  *(float2*)&g_msg[(size_t)(ci0 + ra) * MSG + c0]  = make_float2(m0, m1);
                if (rbr < nE) *(float2*)&g_msg[(size_t)(ci0 + rbr) * MSG + c0] = make_float2(m2, m3);
            }
        }
        #pragma unroll
        for (int mt = 0; mt < 2; mt++) {
            gpa[mt] += __shfl_xor_sync(0xffffffffu, gpa[mt], 1);
            gpa[mt] += __shfl_xor_sync(0xffffffffu, gpa[mt], 2);
            gpb[mt] += __shfl_xor_sync(0xffffffffu, gpb[mt], 1);
            gpb[mt] += __shfl_xor_sync(0xffffffffu, gpb[mt], 2);
        }
        if (qc == 0) {
            #pragma unroll
            for (int mt = 0; mt < 2; mt++) {
                sGate[wn2 * 128 + rb2 + 16 * mt + qr] = gpa[mt];
                sGate[wn2 * 128 + rb2 + 16 * mt + 8 + qr] = gpb[mt];
            }
        }
        __syncthreads();
        if (tid < 128 && tid < nE) {
            float lgv = sGate[tid] + sGate[128 + tid] + sGate[256 + tid] + sGate[384 + tid] + __ldg(bg);
            g_lg[ci0 + tid] = lgv;
            atomicMax(&g_segmax[sR[tid]], f2ord(lgv));
        }
    }
}

// ---------------- fused exp + denom + weighted scatter ----------------
__global__ void k_aggr(const int* __restrict__ rcv) {
    int idx = blockIdx.x * blockDim.x + threadIdx.x;
    int lane = idx & 31;
    int ci = idx >> 5;
    if (ci >= g_cnt) return;
    int e = g_eidx[ci];
    int r = rcv[e];
    float ex = expf(g_lg[ci] - ord2f(g_segmax[r]));
    if (lane == 0) atomicAdd(&g_denom[r], ex);
    float4 m = *(const float4*)&g_msg[(size_t)ci * MSG + lane * 4];
    float* dst = &g_aggr[(size_t)r * MSG + lane * 4];
    asm volatile("red.global.add.v4.f32 [%0], {%1,%2,%3,%4};"
                 :: "l"(dst), "f"(ex * m.x), "f"(ex * m.y), "f"(ex * m.z), "f"(ex * m.w)
                 : "memory");
}

// ---------------- agent MLP head (FFMA fp32, fused divide) ----------------
#define SMEM_AG (2 * 64 * HID * 4)
__global__ __launch_bounds__(256) void k_agent(
    const float* __restrict__ Wh1, const float* __restrict__ bh1,
    const float* __restrict__ Wh2, const float* __restrict__ bh2,
    const float* __restrict__ Wo,  const float* __restrict__ bo,
    float* __restrict__ out)
{
    extern __shared__ float smemf[];
    float* s1 = smemf;
    float* s2 = smemf + 64 * HID;
    __shared__ float sInv[64];

    int a0 = blockIdx.x * 64;
    int tid = threadIdx.x;
    int rg = tid >> 5, lane = tid & 31;
    int r0 = rg * 8;

    if (tid < 64) {
        int a = a0 + tid;
        sInv[tid] = (a < N_AGENTS) ? 1.f / (g_denom[a] + 1e-9f) : 0.f;
    }
    __syncthreads();

    for (int j = tid; j < 64 * (MSG / 4); j += 256) {
        int r = j >> 5, c4 = j & 31;
        int a = a0 + r;
        float4 v = (a < N_AGENTS) ? *((const float4*)g_aggr + (size_t)a * (MSG / 4) + c4)
                                  : make_float4(0.f, 0.f, 0.f, 0.f);
        float inv = sInv[r];
        *(float4*)&s2[r * MSG + c4 * 4] = make_float4(v.x * inv, v.y * inv, v.z * inv, v.w * inv);
    }
    __syncthreads();

    {
        int c0 = lane * 8;
        float acc[8][8];
        {
            float4 u0 = __ldg((const float4*)(bh1 + c0));
            float4 u1 = __ldg((const float4*)(bh1 + c0 + 4));
            float bv[8] = {u0.x,u0.y,u0.z,u0.w,u1.x,u1.y,u1.z,u1.w};
            #pragma unroll
            for (int i = 0; i < 8; i++)
                #pragma unroll
                for (int j = 0; j < 8; j++) acc[i][j] = bv[j];
        }
        for (int k4 = 0; k4 < MSG / 4; k4++) {
            float wv[4][8];
            #pragma unroll
            for (int kk = 0; kk < 4; kk++) {
                const float* wr = Wh1 + (k4 * 4 + kk) * HID + c0;
                float4 u0 = __ldg((const float4*)wr);
                float4 u1 = __ldg((const float4*)(wr + 4));
                wv[kk][0]=u0.x; wv[kk][1]=u0.y; wv[kk][2]=u0.z; wv[kk][3]=u0.w;
                wv[kk][4]=u1.x; wv[kk][5]=u1.y; wv[kk][6]=u1.z; wv[kk][7]=u1.w;
            }
            #pragma unroll
            for (int i = 0; i < 8; i++) {
                float4 a = *(float4*)&s2[(r0 + i) * MSG + k4 * 4];
                float av[4] = {a.x, a.y, a.z, a.w};
                #pragma unroll
                for (int kk = 0; kk < 4; kk++)
                    #pragma unroll
                    for (int j = 0; j < 8; j++) acc[i][j] += av[kk] * wv[kk][j];
            }
        }
        #pragma unroll
        for (int i = 0; i < 8; i++) {
            #pragma unroll
            for (int j = 0; j < 8; j++) acc[i][j] = fmaxf(acc[i][j], 0.f);
            *(float4*)&s1[(r0 + i) * HID + c0]     = make_float4(acc[i][0], acc[i][1], acc[i][2], acc[i][3]);
            *(float4*)&s1[(r0 + i) * HID + c0 + 4] = make_float4(acc[i][4], acc[i][5], acc[i][6], acc[i][7]);
        }
    }
    __syncthreads();

    {
        int c0 = lane * 8;
        float acc[8][8];
        {
            float4 u0 = __ldg((const float4*)(bh2 + c0));
            float4 u1 = __ldg((const float4*)(bh2 + c0 + 4));
            float bv[8] = {u0.x,u0.y,u0.z,u0.w,u1.x,u1.y,u1.z,u1.w};
            #pragma unroll
            for (int i = 0; i < 8; i++)
                #pragma unroll
                for (int j = 0; j < 8; j++) acc[i][j] = bv[j];
        }
        for (int k4 = 0; k4 < HID / 4; k4++) {
            float wv[4][8];
            #pragma unroll
            for (int kk = 0; kk < 4; kk++) {
                const float* wr = Wh2 + (k4 * 4 + kk) * HID + c0;
                float4 u0 = __ldg((const float4*)wr);
                float4 u1 = __ldg((const float4*)(wr + 4));
                wv[kk][0]=u0.x; wv[kk][1]=u0.y; wv[kk][2]=u0.z; wv[kk][3]=u0.w;
                wv[kk][4]=u1.x; wv[kk][5]=u1.y; wv[kk][6]=u1.z; wv[kk][7]=u1.w;
            }
            #pragma unroll
            for (int i = 0; i < 8; i++) {
                float4 a = *(float4*)&s1[(r0 + i) * HID + k4 * 4];
                float av[4] = {a.x, a.y, a.z, a.w};
                #pragma unroll
                for (int kk = 0; kk < 4; kk++)
                    #pragma unroll
                    for (int j = 0; j < 8; j++) acc[i][j] += av[kk] * wv[kk][j];
            }
        }
        __syncthreads();
        #pragma unroll
        for (int i = 0; i < 8; i++) {
            #pragma unroll
            for (int j = 0; j < 8; j++) acc[i][j] = fmaxf(acc[i][j], 0.f);
            *(float4*)&s2[(r0 + i) * HID + c0]     = make_float4(acc[i][0], acc[i][1], acc[i][2], acc[i][3]);
            *(float4*)&s2[(r0 + i) * HID + c0 + 4] = make_float4(acc[i][4], acc[i][5], acc[i][6], acc[i][7]);
        }
    }
    __syncthreads();

    {
        float wv[8];
        #pragma unroll
        for (int j = 0; j < 8; j++) wv[j] = __ldg(Wo + lane + 32 * j);
        float bov = __ldg(bo);
        #pragma unroll
        for (int i = 0; i < 8; i++) {
            int rw = r0 + i;
            float p = 0.f;
            #pragma unroll
            for (int j = 0; j < 8; j++) p += s2[rw * HID + lane + 32 * j] * wv[j];
            #pragma unroll
            for (int off = 16; off > 0; off >>= 1) p += __shfl_xor_sync(0xffffffffu, p, off);
            int a = a0 + rw;
            if (lane == 0 && a < N_AGENTS) out[a] = tanhf(p + bov);
        }
    }
}

// ---------------- launch ----------------
extern "C" void kernel_launch(void* const* d_in, const int* in_sizes, int n_in,
                              void* d_out, int out_size)
{
    const float* node = (const float*)d_in[0];
    const float* ef   = (const float*)d_in[1];
    const float* W1   = (const float*)d_in[2];
    const float* b1   = (const float*)d_in[3];
    const float* W2   = (const float*)d_in[4];
    const float* b2   = (const float*)d_in[5];
    const float* wg   = (const float*)d_in[6];
    const float* bg   = (const float*)d_in[7];
    const float* Wh1  = (const float*)d_in[8];
    const float* bh1  = (const float*)d_in[9];
    const float* Wh2  = (const float*)d_in[10];
    const float* bh2  = (const float*)d_in[11];
    const float* Wo   = (const float*)d_in[12];
    const float* bo   = (const float*)d_in[13];
    const int*   snd  = (const int*)d_in[14];
    const int*   rcv  = (const int*)d_in[15];
    float* out = (float*)d_out;

    cudaFuncSetAttribute(k_edge_mma, cudaFuncAttributeMaxDynamicSharedMemorySize, SMEM_EDGE);
    cudaFuncSetAttribute(k_agent,    cudaFuncAttributeMaxDynamicSharedMemorySize, SMEM_AG);

    k_init<<<12500, 256>>>();
    k_compact<<<(N_EDGESC + 255) / 256, 256>>>(rcv);
    k_prep<<<(160 * 256 + 256 * 128 + 255) / 256, 256>>>(W1, W2);
    k_edge_mma<<<(N_EDGESC + 127) / 128, 512, SMEM_EDGE>>>(node, ef, b1, b2, wg, bg, snd, rcv);
    k_aggr<<<(N_EDGESC * 32) / 256, 256>>>(rcv);
    k_agent<<<(N_AGENTS + 63) / 64, 256, SMEM_AG>>>(Wh1, bh1, Wh2, bh2, Wo, bo, out);
}

// round 8
// speedup vs baseline: 1.7129x; 1.0572x over previous
#include <cuda_runtime.h>
#include <math.h>
#include <stdint.h>

#define N_NODES  50000
#define N_EDGESC 800000
#define ND       64
#define ED       32
#define MSG      128
#define HID      256
#define N_AGENTS 25000

// ---------------- scratch ----------------
__device__ float        g_msg[(size_t)N_EDGESC * MSG];
__device__ float        g_lg[N_EDGESC];
__device__ int          g_eidx[N_EDGESC];
__device__ int          g_cnt;
__device__ unsigned int g_segmax[N_AGENTS];
__device__ float        g_denom[N_AGENTS];
__device__ float        g_aggr[(size_t)N_AGENTS * MSG];
// pre-swizzled tf32 "pair planes": slot s=4*(k>>3)+(k&3), comp=(k>>2)&1
__device__ __align__(16) float g_W1p[80 * 520];    // 260 float2 (n<256) per slot-row
__device__ __align__(16) float g_W2p[128 * 264];   // 132 float2 (n<128) per slot-row

__device__ __forceinline__ unsigned f2ord(float f) {
    unsigned u = __float_as_uint(f);
    return (u & 0x80000000u) ? ~u : (u | 0x80000000u);
}
__device__ __forceinline__ float ord2f(unsigned o) {
    unsigned u = (o & 0x80000000u) ? (o & 0x7fffffffu) : ~o;
    return __uint_as_float(u);
}
__device__ __forceinline__ float tf32r(float x) {
    uint32_t u;
    asm("cvt.rna.tf32.f32 %0, %1;" : "=r"(u) : "f"(x));
    return __uint_as_float(u);
}
__device__ __forceinline__ void mma168(float* d, const uint32_t* a, const uint32_t* b) {
    asm volatile(
        "mma.sync.aligned.m16n8k8.row.col.f32.tf32.tf32.f32 "
        "{%0,%1,%2,%3}, {%4,%5,%6,%7}, {%8,%9}, {%0,%1,%2,%3};"
        : "+f"(d[0]), "+f"(d[1]), "+f"(d[2]), "+f"(d[3])
        : "r"(a[0]), "r"(a[1]), "r"(a[2]), "r"(a[3]), "r"(b[0]), "r"(b[1]));
}
__device__ __forceinline__ void cp16(uint32_t dst, const void* src) {
    asm volatile("cp.async.cg.shared.global [%0], [%1], 16;" :: "r"(dst), "l"(src) : "memory");
}
#define CP_COMMIT() asm volatile("cp.async.commit_group;" ::: "memory")
#define CP_WAIT1()  asm volatile("cp.async.wait_group 1;" ::: "memory")

// ---------------- init / compact / prep ----------------
__global__ void k_init() {
    int i = blockIdx.x * blockDim.x + threadIdx.x;
    int stride = gridDim.x * blockDim.x;
    for (int j = i; j < N_AGENTS * MSG; j += stride) g_aggr[j] = 0.f;
    if (i < N_AGENTS) { g_segmax[i] = 0u; g_denom[i] = 0.f; }
    if (i == 0) g_cnt = 0;
}
__global__ void k_compact(const int* __restrict__ rcv) {
    int e = blockIdx.x * blockDim.x + threadIdx.x;
    if (e < N_EDGESC && rcv[e] < N_AGENTS) {
        int p = atomicAdd(&g_cnt, 1);
        g_eidx[p] = e;
    }
}
__global__ void k_prep(const float* __restrict__ W1, const float* __restrict__ W2) {
    int i = blockIdx.x * blockDim.x + threadIdx.x;
    if (i < 160 * 256) {
        int k = i >> 8, n = i & 255;
        int slot = 4 * (k >> 3) + (k & 3);
        int comp = (k >> 2) & 1;
        g_W1p[slot * 520 + 2 * n + comp] = tf32r(W1[(size_t)k * HID + n]);
    }
    int j = i - 160 * 256;
    if (j >= 0 && j < 256 * 128) {
        int k = j >> 7, n = j & 127;
        int slot = 4 * (k >> 3) + (k & 3);
        int comp = (k >> 2) & 1;
        g_W2p[slot * 264 + 2 * n + comp] = tf32r(W2[(size_t)k * MSG + n]);
    }
}

// ---------------- fused edge MLP: 64-edge tiles, 256 threads, 2 CTAs/SM ----------------
// pair strides: row-stride bytes mod 128 == 32 -> conflict-free A-frag lds.64
#define SA_STR2  84             // sA pair row stride (float2); 672 B/row
#define SH_STR2  132            // sH pair row stride (float2); 1056 B/row
#define WBUF_STR 16640          // GEMM1 chunk 8 slot-rows x 520 f; GEMM2 chunk (8448 B) fits too
#define OFF_AH   0              // union: sA 64*672=43008 / sH 64*1056=67584
#define OFF_WB   67584          // 2 x 16640 = 33280
#define OFF_EG   100864         // 64 int
#define OFF_S    101120
#define OFF_R    101376
#define OFF_B1   101632         // 256 f
#define OFF_B2   102656         // 128 f
#define OFF_WG   103168         // 128 f
#define OFF_GATE 103680         // 4 x 64 f
#define SMEM_EDGE 104704

__global__ __launch_bounds__(256, 2) void k_edge_mma(
    const float* __restrict__ nf, const float* __restrict__ ef,
    const float* __restrict__ b1, const float* __restrict__ b2,
    const float* __restrict__ wg, const float* __restrict__ bg,
    const int* __restrict__ snd, const int* __restrict__ rcv)
{
    extern __shared__ char smem[];
    uint32_t sb;
    asm("{ .reg .u64 t; cvta.to.shared.u64 t, %1; cvt.u32.u64 %0, t; }" : "=r"(sb) : "l"(smem));

    float* sAf = (float*)(smem + OFF_AH);
    int*   sEg = (int*)(smem + OFF_EG);
    int*   sS  = (int*)(smem + OFF_S);
    int*   sR  = (int*)(smem + OFF_R);
    float* sB1 = (float*)(smem + OFF_B1);
    float* sB2 = (float*)(smem + OFF_B2);
    float* sWg = (float*)(smem + OFF_WG);
    float* sGate = (float*)(smem + OFF_GATE);

    int cnt = g_cnt;
    int ci0 = blockIdx.x * 64;
    if (ci0 >= cnt) return;
    int nE = min(64, cnt - ci0);

    int tid = threadIdx.x;
    int wid = tid >> 5, lane = tid & 31;
    int qr = lane >> 2, qc = lane & 3;

    // prime W1 chunk0 -> buf0 (overlaps gather)
    {
        const float4* src = (const float4*)g_W1p;
        uint32_t dst = sb + OFF_WB;
        for (int j = tid; j < 1040; j += 256) cp16(dst + j * 16, src + j);
        CP_COMMIT();
    }

    if (tid < 64) {
        int e = (tid < nE) ? g_eidx[ci0 + tid] : g_eidx[ci0];
        sEg[tid] = e;
        sS[tid] = snd[e];
        sR[tid] = rcv[e];
    }
    sB1[tid] = __ldg(b1 + tid);
    if (tid < 128) { sB2[tid] = __ldg(b2 + tid); sWg[tid] = __ldg(wg + tid); }
    __syncthreads();

    // gather A tile [nf[s]|nf[r]|ef] into pair layout
    for (int i = tid; i < 64 * 40; i += 256) {
        int r = i / 40, q = i % 40;
        float4 v;
        int cb;
        if (q < 16)      { v = __ldg((const float4*)(nf + (size_t)sS[r] * ND) + q);         cb = 4 * q; }
        else if (q < 32) { v = __ldg((const float4*)(nf + (size_t)sR[r] * ND) + (q - 16));  cb = 64 + 4 * (q - 16); }
        else             { v = __ldg((const float4*)(ef + (size_t)sEg[r] * ED) + (q - 32)); cb = 128 + 4 * (q - 32); }
        int g = cb >> 3, comp = (cb >> 2) & 1;
        float* p = sAf + r * (2 * SA_STR2) + 8 * g + comp;
        p[0] = tf32r(v.x); p[2] = tf32r(v.y); p[4] = tf32r(v.z); p[6] = tf32r(v.w);
    }

    // ---- GEMM1: 64x256, K=160. Warp grid 1x8: Mw=64, Nw=32 ----
    int cb1 = 32 * wid;

    float acc1[4][4][4];
    #pragma unroll
    for (int mt = 0; mt < 4; mt++)
        #pragma unroll
        for (int nt = 0; nt < 4; nt++)
            #pragma unroll
            for (int j = 0; j < 4; j++) acc1[mt][nt][j] = 0.f;

    const float2* sAp = (const float2*)sAf;
    for (int kc = 0; kc < 10; kc++) {
        __syncthreads();            // all reads of buf[(kc+1)&1] (chunk kc-1) complete
        if (kc + 1 < 10) {
            const float4* src = (const float4*)g_W1p + (size_t)(kc + 1) * 1040;
            uint32_t dst = sb + OFF_WB + ((kc + 1) & 1) * WBUF_STR;
            for (int j = tid; j < 1040; j += 256) cp16(dst + j * 16, src + j);
        }
        CP_COMMIT();
        CP_WAIT1();                 // chunk kc arrived
        __syncthreads();
        const float2* wb = (const float2*)(smem + OFF_WB + (kc & 1) * WBUF_STR);
        #pragma unroll
        for (int kbl = 0; kbl < 2; kbl++) {
            int aslot = 4 * (2 * kc + kbl) + qc;
            uint32_t af[4][4];
            #pragma unroll
            for (int mt = 0; mt < 4; mt++) {
                float2 a0 = sAp[(16 * mt + qr) * SA_STR2 + aslot];
                float2 a1 = sAp[(16 * mt + 8 + qr) * SA_STR2 + aslot];
                af[mt][0] = __float_as_uint(a0.x); af[mt][1] = __float_as_uint(a1.x);
                af[mt][2] = __float_as_uint(a0.y); af[mt][3] = __float_as_uint(a1.y);
            }
            int srow = 4 * kbl + qc;
            uint32_t bf[4][2];
            #pragma unroll
            for (int nt = 0; nt < 4; nt++) {
                float2 bv = wb[srow * 260 + cb1 + 8 * nt + qr];
                bf[nt][0] = __float_as_uint(bv.x); bf[nt][1] = __float_as_uint(bv.y);
            }
            #pragma unroll
            for (int mt = 0; mt < 4; mt++)
                #pragma unroll
                for (int nt = 0; nt < 4; nt++)
                    mma168(acc1[mt][nt], af[mt], bf[nt]);
        }
    }
    __syncthreads();   // all GEMM1 reads of sA / W bufs done

    // prime W2 chunk0 -> buf0 (overlaps epilogue1)
    {
        const float4* src = (const float4*)g_W2p;
        uint32_t dst = sb + OFF_WB;
        for (int j = tid; j < 528; j += 256) cp16(dst + j * 16, src + j);
        CP_COMMIT();
    }

    // epilogue1: h = tf32(relu(acc + b1)) -> sH pair layout (overwrites sA region)
    float* sHf = sAf;
    #pragma unroll
    for (int mt = 0; mt < 4; mt++) {
        int ra = 16 * mt + qr, rbr = ra + 8;
        #pragma unroll
        for (int nt = 0; nt < 4; nt++) {
            int c0 = cb1 + 8 * nt + 2 * qc;
            float bb0 = sB1[c0], bb1 = sB1[c0 + 1];
            float* d = acc1[mt][nt];
            #pragma unroll
            for (int u = 0; u < 2; u++) {
                int c = c0 + u;
                int g = c >> 3, e = c & 7;
                int idx = 8 * g + 2 * (e & 3) + (e >> 2);
                sHf[ra * (2 * SH_STR2) + idx]  = tf32r(fmaxf(d[u] + (u ? bb1 : bb0), 0.f));
                sHf[rbr * (2 * SH_STR2) + idx] = tf32r(fmaxf(d[2 + u] + (u ? bb1 : bb0), 0.f));
            }
        }
    }

    // ---- GEMM2: 64x128, K=256. Warp grid 2x4: Mw=32, Nw=32 ----
    int wm2 = wid & 1, wn2 = wid >> 1;
    int rb2 = 32 * wm2, cb2 = 32 * wn2;

    float acc2[2][4][4];
    #pragma unroll
    for (int mt = 0; mt < 2; mt++)
        #pragma unroll
        for (int nt = 0; nt < 4; nt++)
            #pragma unroll
            for (int j = 0; j < 4; j++) acc2[mt][nt][j] = 0.f;

    const float2* sHp = (const float2*)sHf;
    for (int kc = 0; kc < 16; kc++) {
        __syncthreads();            // epilogue1 writes visible (kc=0); buf[(kc+1)&1] free
        if (kc + 1 < 16) {
            const float4* src = (const float4*)g_W2p + (size_t)(kc + 1) * 528;
            uint32_t dst = sb + OFF_WB + ((kc + 1) & 1) * WBUF_STR;
            for (int j = tid; j < 528; j += 256) cp16(dst + j * 16, src + j);
        }
        CP_COMMIT();
        CP_WAIT1();
        __syncthreads();
        const float2* wb = (const float2*)(smem + OFF_WB + (kc & 1) * WBUF_STR);
        #pragma unroll
        for (int kbl = 0; kbl < 2; kbl++) {
            int aslot = 4 * (2 * kc + kbl) + qc;
            uint32_t af[2][4];
            #pragma unroll
            for (int mt = 0; mt < 2; mt++) {
                float2 a0 = sHp[(rb2 + 16 * mt + qr) * SH_STR2 + aslot];
                float2 a1 = sHp[(rb2 + 16 * mt + 8 + qr) * SH_STR2 + aslot];
                af[mt][0] = __float_as_uint(a0.x); af[mt][1] = __float_as_uint(a1.x);
                af[mt][2] = __float_as_uint(a0.y); af[mt][3] = __float_as_uint(a1.y);
            }
            int srow = 4 * kbl + qc;
            uint32_t bf[4][2];
            #pragma unroll
            for (int nt = 0; nt < 4; nt++) {
                float2 bv = wb[srow * 132 + cb2 + 8 * nt + qr];
                bf[nt][0] = __float_as_uint(bv.x); bf[nt][1] = __float_as_uint(bv.y);
            }
            #pragma unroll
            for (int mt = 0; mt < 2; mt++)
                #pragma unroll
                for (int nt = 0; nt < 4; nt++)
                    mma168(acc2[mt][nt], af[mt], bf[nt]);
        }
    }

    // epilogue2: msg = relu(acc2 + b2); gate partials; segmax; store
    {
        float gpa[2] = {0.f, 0.f}, gpb[2] = {0.f, 0.f};
        #pragma unroll
        for (int mt = 0; mt < 2; mt++) {
            int ra = rb2 + 16 * mt + qr, rbr = ra + 8;
            #pragma unroll
            for (int nt = 0; nt < 4; nt++) {
                int c0 = cb2 + 8 * nt + 2 * qc;
                float bb0 = sB2[c0], bb1 = sB2[c0 + 1];
                float w0 = sWg[c0], w1 = sWg[c0 + 1];
                float* d = acc2[mt][nt];
                float m0 = fmaxf(d[0] + bb0, 0.f);
                float m1 = fmaxf(d[1] + bb1, 0.f);
                float m2 = fmaxf(d[2] + bb0, 0.f);
                float m3 = fmaxf(d[3] + bb1, 0.f);
                gpa[mt] += m0 * w0 + m1 * w1;
                gpb[mt] += m2 * w0 + m3 * w1;
                if (ra < nE)  *(float2*)&g_msg[(size_t)(ci0 + ra) * MSG + c0]  = make_float2(m0, m1);
                if (rbr < nE) *(float2*)&g_msg[(size_t)(ci0 + rbr) * MSG + c0] = make_float2(m2, m3);
            }
        }
        #pragma unroll
        for (int mt = 0; mt < 2; mt++) {
            gpa[mt] += __shfl_xor_sync(0xffffffffu, gpa[mt], 1);
            gpa[mt] += __shfl_xor_sync(0xffffffffu, gpa[mt], 2);
            gpb[mt] += __shfl_xor_sync(0xffffffffu, gpb[mt], 1);
            gpb[mt] += __shfl_xor_sync(0xffffffffu, gpb[mt], 2);
        }
        if (qc == 0) {
            #pragma unroll
            for (int mt = 0; mt < 2; mt++) {
                sGate[wn2 * 64 + rb2 + 16 * mt + qr] = gpa[mt];
                sGate[wn2 * 64 + rb2 + 16 * mt + 8 + qr] = gpb[mt];
            }
        }
        __syncthreads();
        if (tid < 64 && tid < nE) {
            float lgv = sGate[tid] + sGate[64 + tid] + sGate[128 + tid] + sGate[192 + tid] + __ldg(bg);
            g_lg[ci0 + tid] = lgv;
            atomicMax(&g_segmax[sR[tid]], f2ord(lgv));
        }
    }
}

// ---------------- fused exp + denom + weighted scatter ----------------
__global__ void k_aggr(const int* __restrict__ rcv) {
    int idx = blockIdx.x * blockDim.x + threadIdx.x;
    int lane = idx & 31;
    int ci = idx >> 5;
    if (ci >= g_cnt) return;
    int e = g_eidx[ci];
    int r = rcv[e];
    float ex = expf(g_lg[ci] - ord2f(g_segmax[r]));
    if (lane == 0) atomicAdd(&g_denom[r], ex);
    float4 m = *(const float4*)&g_msg[(size_t)ci * MSG + lane * 4];
    float* dst = &g_aggr[(size_t)r * MSG + lane * 4];
    asm volatile("red.global.add.v4.f32 [%0], {%1,%2,%3,%4};"
                 :: "l"(dst), "f"(ex * m.x), "f"(ex * m.y), "f"(ex * m.z), "f"(ex * m.w)
                 : "memory");
}

// ---------------- agent MLP head (FFMA fp32, fused divide) ----------------
#define SMEM_AG (2 * 64 * HID * 4)
__global__ __launch_bounds__(256) void k_agent(
    const float* __restrict__ Wh1, const float* __restrict__ bh1,
    const float* __restrict__ Wh2, const float* __restrict__ bh2,
    const float* __restrict__ Wo,  const float* __restrict__ bo,
    float* __restrict__ out)
{
    extern __shared__ float smemf[];
    float* s1 = smemf;
    float* s2 = smemf + 64 * HID;
    __shared__ float sInv[64];

    int a0 = blockIdx.x * 64;
    int tid = threadIdx.x;
    int rg = tid >> 5, lane = tid & 31;
    int r0 = rg * 8;

    if (tid < 64) {
        int a = a0 + tid;
        sInv[tid] = (a < N_AGENTS) ? 1.f / (g_denom[a] + 1e-9f) : 0.f;
    }
    __syncthreads();

    for (int j = tid; j < 64 * (MSG / 4); j += 256) {
        int r = j >> 5, c4 = j & 31;
        int a = a0 + r;
        float4 v = (a < N_AGENTS) ? *((const float4*)g_aggr + (size_t)a * (MSG / 4) + c4)
                                  : make_float4(0.f, 0.f, 0.f, 0.f);
        float inv = sInv[r];
        *(float4*)&s2[r * MSG + c4 * 4] = make_float4(v.x * inv, v.y * inv, v.z * inv, v.w * inv);
    }
    __syncthreads();

    {
        int c0 = lane * 8;
        float acc[8][8];
        {
            float4 u0 = __ldg((const float4*)(bh1 + c0));
            float4 u1 = __ldg((const float4*)(bh1 + c0 + 4));
            float bv[8] = {u0.x,u0.y,u0.z,u0.w,u1.x,u1.y,u1.z,u1.w};
            #pragma unroll
            for (int i = 0; i < 8; i++)
                #pragma unroll
                for (int j = 0; j < 8; j++) acc[i][j] = bv[j];
        }
        for (int k4 = 0; k4 < MSG / 4; k4++) {
            float wv[4][8];
            #pragma unroll
            for (int kk = 0; kk < 4; kk++) {
                const float* wr = Wh1 + (k4 * 4 + kk) * HID + c0;
                float4 u0 = __ldg((const float4*)wr);
                float4 u1 = __ldg((const float4*)(wr + 4));
                wv[kk][0]=u0.x; wv[kk][1]=u0.y; wv[kk][2]=u0.z; wv[kk][3]=u0.w;
                wv[kk][4]=u1.x; wv[kk][5]=u1.y; wv[kk][6]=u1.z; wv[kk][7]=u1.w;
            }
            #pragma unroll
            for (int i = 0; i < 8; i++) {
                float4 a = *(float4*)&s2[(r0 + i) * MSG + k4 * 4];
                float av[4] = {a.x, a.y, a.z, a.w};
                #pragma unroll
                for (int kk = 0; kk < 4; kk++)
                    #pragma unroll
                    for (int j = 0; j < 8; j++) acc[i][j] += av[kk] * wv[kk][j];
            }
        }
        #pragma unroll
        for (int i = 0; i < 8; i++) {
            #pragma unroll
            for (int j = 0; j < 8; j++) acc[i][j] = fmaxf(acc[i][j], 0.f);
            *(float4*)&s1[(r0 + i) * HID + c0]     = make_float4(acc[i][0], acc[i][1], acc[i][2], acc[i][3]);
            *(float4*)&s1[(r0 + i) * HID + c0 + 4] = make_float4(acc[i][4], acc[i][5], acc[i][6], acc[i][7]);
        }
    }
    __syncthreads();

    {
        int c0 = lane * 8;
        float acc[8][8];
        {
            float4 u0 = __ldg((const float4*)(bh2 + c0));
            float4 u1 = __ldg((const float4*)(bh2 + c0 + 4));
            float bv[8] = {u0.x,u0.y,u0.z,u0.w,u1.x,u1.y,u1.z,u1.w};
            #pragma unroll
            for (int i = 0; i < 8; i++)
                #pragma unroll
                for (int j = 0; j < 8; j++) acc[i][j] = bv[j];
        }
        for (int k4 = 0; k4 < HID / 4; k4++) {
            float wv[4][8];
            #pragma unroll
            for (int kk = 0; kk < 4; kk++) {
                const float* wr = Wh2 + (k4 * 4 + kk) * HID + c0;
                float4 u0 = __ldg((const float4*)wr);
                float4 u1 = __ldg((const float4*)(wr + 4));
                wv[kk][0]=u0.x; wv[kk][1]=u0.y; wv[kk][2]=u0.z; wv[kk][3]=u0.w;
                wv[kk][4]=u1.x; wv[kk][5]=u1.y; wv[kk][6]=u1.z; wv[kk][7]=u1.w;
            }
            #pragma unroll
            for (int i = 0; i < 8; i++) {
                float4 a = *(float4*)&s1[(r0 + i) * HID + k4 * 4];
                float av[4] = {a.x, a.y, a.z, a.w};
                #pragma unroll
                for (int kk = 0; kk < 4; kk++)
                    #pragma unroll
                    for (int j = 0; j < 8; j++) acc[i][j] += av[kk] * wv[kk][j];
            }
        }
        __syncthreads();
        #pragma unroll
        for (int i = 0; i < 8; i++) {
            #pragma unroll
            for (int j = 0; j < 8; j++) acc[i][j] = fmaxf(acc[i][j], 0.f);
            *(float4*)&s2[(r0 + i) * HID + c0]     = make_float4(acc[i][0], acc[i][1], acc[i][2], acc[i][3]);
            *(float4*)&s2[(r0 + i) * HID + c0 + 4] = make_float4(acc[i][4], acc[i][5], acc[i][6], acc[i][7]);
        }
    }
    __syncthreads();

    {
        float wv[8];
        #pragma unroll
        for (int j = 0; j < 8; j++) wv[j] = __ldg(Wo + lane + 32 * j);
        float bov = __ldg(bo);
        #pragma unroll
        for (int i = 0; i < 8; i++) {
            int rw = r0 + i;
            float p = 0.f;
            #pragma unroll
            for (int j = 0; j < 8; j++) p += s2[rw * HID + lane + 32 * j] * wv[j];
            #pragma unroll
            for (int off = 16; off > 0; off >>= 1) p += __shfl_xor_sync(0xffffffffu, p, off);
            int a = a0 + rw;
            if (lane == 0 && a < N_AGENTS) out[a] = tanhf(p + bov);
        }
    }
}

// ---------------- launch ----------------
extern "C" void kernel_launch(void* const* d_in, const int* in_sizes, int n_in,
                              void* d_out, int out_size)
{
    const float* node = (const float*)d_in[0];
    const float* ef   = (const float*)d_in[1];
    const float* W1   = (const float*)d_in[2];
    const float* b1   = (const float*)d_in[3];
    const float* W2   = (const float*)d_in[4];
    const float* b2   = (const float*)d_in[5];
    const float* wg   = (const float*)d_in[6];
    const float* bg   = (const float*)d_in[7];
    const float* Wh1  = (const float*)d_in[8];
    const float* bh1  = (const float*)d_in[9];
    const float* Wh2  = (const float*)d_in[10];
    const float* bh2  = (const float*)d_in[11];
    const float* Wo   = (const float*)d_in[12];
    const float* bo   = (const float*)d_in[13];
    const int*   snd  = (const int*)d_in[14];
    const int*   rcv  = (const int*)d_in[15];
    float* out = (float*)d_out;

    cudaFuncSetAttribute(k_edge_mma, cudaFuncAttributeMaxDynamicSharedMemorySize, SMEM_EDGE);
    cudaFuncSetAttribute(k_agent,    cudaFuncAttributeMaxDynamicSharedMemorySize, SMEM_AG);

    k_init<<<12500, 256>>>();
    k_compact<<<(N_EDGESC + 255) / 256, 256>>>(rcv);
    k_prep<<<(160 * 256 + 256 * 128 + 255) / 256, 256>>>(W1, W2);
    k_edge_mma<<<(N_EDGESC + 63) / 64, 256, SMEM_EDGE>>>(node, ef, b1, b2, wg, bg, snd, rcv);
    k_aggr<<<(N_EDGESC * 32) / 256, 256>>>(rcv);
    k_agent<<<(N_AGENTS + 63) / 64, 256, SMEM_AG>>>(Wh1, bh1, Wh2, bh2, Wo, bo, out);
}

// round 9
// speedup vs baseline: 1.9907x; 1.1622x over previous
#include <cuda_runtime.h>
#include <math.h>
#include <stdint.h>

#define N_NODES  50000
#define N_EDGESC 800000
#define ND       64
#define ED       32
#define MSG      128
#define HID      256
#define N_AGENTS 25000

// ---------------- scratch ----------------
__device__ int          g_eidx[N_EDGESC];
__device__ int          g_cnt;
__device__ float        g_denom[N_AGENTS];
__device__ float        g_aggr[(size_t)N_AGENTS * MSG];
// pre-swizzled tf32 "pair planes": slot s=4*(k>>3)+(k&3), comp=(k>>2)&1
__device__ __align__(16) float g_W1p[80 * 520];    // 260 float2 (n<256) per slot-row
__device__ __align__(16) float g_W2p[128 * 264];   // 132 float2 (n<128) per slot-row

__device__ __forceinline__ float tf32r(float x) {
    uint32_t u;
    asm("cvt.rna.tf32.f32 %0, %1;" : "=r"(u) : "f"(x));
    return __uint_as_float(u);
}
__device__ __forceinline__ void mma168(float* d, const uint32_t* a, const uint32_t* b) {
    asm volatile(
        "mma.sync.aligned.m16n8k8.row.col.f32.tf32.tf32.f32 "
        "{%0,%1,%2,%3}, {%4,%5,%6,%7}, {%8,%9}, {%0,%1,%2,%3};"
        : "+f"(d[0]), "+f"(d[1]), "+f"(d[2]), "+f"(d[3])
        : "r"(a[0]), "r"(a[1]), "r"(a[2]), "r"(a[3]), "r"(b[0]), "r"(b[1]));
}
__device__ __forceinline__ void cp16(uint32_t dst, const void* src) {
    asm volatile("cp.async.cg.shared.global [%0], [%1], 16;" :: "r"(dst), "l"(src) : "memory");
}
#define CP_COMMIT() asm volatile("cp.async.commit_group;" ::: "memory")
#define CP_WAIT1()  asm volatile("cp.async.wait_group 1;" ::: "memory")
__device__ __forceinline__ void red2(float* dst, float x, float y) {
    asm volatile("red.global.add.v2.f32 [%0], {%1,%2};" :: "l"(dst), "f"(x), "f"(y) : "memory");
}

// ---------------- init / compact / prep ----------------
__global__ void k_init() {
    int i = blockIdx.x * blockDim.x + threadIdx.x;
    int stride = gridDim.x * blockDim.x;
    for (int j = i; j < N_AGENTS * MSG; j += stride) g_aggr[j] = 0.f;
    if (i < N_AGENTS) g_denom[i] = 0.f;
    if (i == 0) g_cnt = 0;
}
__global__ void k_compact(const int* __restrict__ rcv) {
    int e = blockIdx.x * blockDim.x + threadIdx.x;
    if (e < N_EDGESC && rcv[e] < N_AGENTS) {
        int p = atomicAdd(&g_cnt, 1);
        g_eidx[p] = e;
    }
}
__global__ void k_prep(const float* __restrict__ W1, const float* __restrict__ W2) {
    int i = blockIdx.x * blockDim.x + threadIdx.x;
    if (i < 160 * 256) {
        int k = i >> 8, n = i & 255;
        int slot = 4 * (k >> 3) + (k & 3);
        int comp = (k >> 2) & 1;
        g_W1p[slot * 520 + 2 * n + comp] = tf32r(W1[(size_t)k * HID + n]);
    }
    int j = i - 160 * 256;
    if (j >= 0 && j < 256 * 128) {
        int k = j >> 7, n = j & 127;
        int slot = 4 * (k >> 3) + (k & 3);
        int comp = (k >> 2) & 1;
        g_W2p[slot * 264 + 2 * n + comp] = tf32r(W2[(size_t)k * MSG + n]);
    }
}

// ---------------- fused edge MLP + softmax-numerator scatter ----------------
#define SA_STR2  84             // sA pair row stride (float2); 672 B/row (mod 128 = 32)
#define SH_STR2  132            // sH pair row stride (float2); 1056 B/row
#define WBUF_STR 16640
#define OFF_AH   0              // union: sA 43008 / sH 67584
#define OFF_WB   67584          // 2 x 16640
#define OFF_EG   100864
#define OFF_S    101120
#define OFF_R    101376
#define OFF_B1   101632
#define OFF_B2   102656
#define OFF_WG   103168
#define OFF_GATE 103680         // 4 x 64 f (then ex in [0..63])
#define SMEM_EDGE 104704

__global__ __launch_bounds__(256, 2) void k_edge_mma(
    const float* __restrict__ nf, const float* __restrict__ ef,
    const float* __restrict__ b1, const float* __restrict__ b2,
    const float* __restrict__ wg, const float* __restrict__ bg,
    const int* __restrict__ snd, const int* __restrict__ rcv)
{
    extern __shared__ char smem[];
    uint32_t sb;
    asm("{ .reg .u64 t; cvta.to.shared.u64 t, %1; cvt.u32.u64 %0, t; }" : "=r"(sb) : "l"(smem));

    float* sAf = (float*)(smem + OFF_AH);
    int*   sEg = (int*)(smem + OFF_EG);
    int*   sS  = (int*)(smem + OFF_S);
    int*   sR  = (int*)(smem + OFF_R);
    float* sB1 = (float*)(smem + OFF_B1);
    float* sB2 = (float*)(smem + OFF_B2);
    float* sWg = (float*)(smem + OFF_WG);
    float* sGate = (float*)(smem + OFF_GATE);

    int cnt = g_cnt;
    int ci0 = blockIdx.x * 64;
    if (ci0 >= cnt) return;
    int nE = min(64, cnt - ci0);

    int tid = threadIdx.x;
    int wid = tid >> 5, lane = tid & 31;
    int qr = lane >> 2, qc = lane & 3;

    // prime W1 chunk0 -> buf0
    {
        const float4* src = (const float4*)g_W1p;
        uint32_t dst = sb + OFF_WB;
        for (int j = tid; j < 1040; j += 256) cp16(dst + j * 16, src + j);
        CP_COMMIT();
    }

    if (tid < 64) {
        int e = (tid < nE) ? g_eidx[ci0 + tid] : g_eidx[ci0];
        sEg[tid] = e;
        sS[tid] = snd[e];
        sR[tid] = rcv[e];
    }
    sB1[tid] = __ldg(b1 + tid);
    if (tid < 128) { sB2[tid] = __ldg(b2 + tid); sWg[tid] = __ldg(wg + tid); }
    __syncthreads();

    // gather A tile [nf[s]|nf[r]|ef] into pair layout
    for (int i = tid; i < 64 * 40; i += 256) {
        int r = i / 40, q = i % 40;
        float4 v;
        int cb;
        if (q < 16)      { v = __ldg((const float4*)(nf + (size_t)sS[r] * ND) + q);         cb = 4 * q; }
        else if (q < 32) { v = __ldg((const float4*)(nf + (size_t)sR[r] * ND) + (q - 16));  cb = 64 + 4 * (q - 16); }
        else             { v = __ldg((const float4*)(ef + (size_t)sEg[r] * ED) + (q - 32)); cb = 128 + 4 * (q - 32); }
        int g = cb >> 3, comp = (cb >> 2) & 1;
        float* p = sAf + r * (2 * SA_STR2) + 8 * g + comp;
        p[0] = tf32r(v.x); p[2] = tf32r(v.y); p[4] = tf32r(v.z); p[6] = tf32r(v.w);
    }

    // ---- GEMM1: 64x256, K=160. Warp grid 1x8: Mw=64, Nw=32 ----
    int cb1 = 32 * wid;

    float acc1[4][4][4];
    #pragma unroll
    for (int mt = 0; mt < 4; mt++)
        #pragma unroll
        for (int nt = 0; nt < 4; nt++)
            #pragma unroll
            for (int j = 0; j < 4; j++) acc1[mt][nt][j] = 0.f;

    const float2* sAp = (const float2*)sAf;
    for (int kc = 0; kc < 10; kc++) {
        __syncthreads();
        if (kc + 1 < 10) {
            const float4* src = (const float4*)g_W1p + (size_t)(kc + 1) * 1040;
            uint32_t dst = sb + OFF_WB + ((kc + 1) & 1) * WBUF_STR;
            for (int j = tid; j < 1040; j += 256) cp16(dst + j * 16, src + j);
        }
        CP_COMMIT();
        CP_WAIT1();
        __syncthreads();
        const float2* wb = (const float2*)(smem + OFF_WB + (kc & 1) * WBUF_STR);
        #pragma unroll
        for (int kbl = 0; kbl < 2; kbl++) {
            int aslot = 4 * (2 * kc + kbl) + qc;
            uint32_t af[4][4];
            #pragma unroll
            for (int mt = 0; mt < 4; mt++) {
                float2 a0 = sAp[(16 * mt + qr) * SA_STR2 + aslot];
                float2 a1 = sAp[(16 * mt + 8 + qr) * SA_STR2 + aslot];
                af[mt][0] = __float_as_uint(a0.x); af[mt][1] = __float_as_uint(a1.x);
                af[mt][2] = __float_as_uint(a0.y); af[mt][3] = __float_as_uint(a1.y);
            }
            int srow = 4 * kbl + qc;
            uint32_t bf[4][2];
            #pragma unroll
            for (int nt = 0; nt < 4; nt++) {
                float2 bv = wb[srow * 260 + cb1 + 8 * nt + qr];
                bf[nt][0] = __float_as_uint(bv.x); bf[nt][1] = __float_as_uint(bv.y);
            }
            #pragma unroll
            for (int mt = 0; mt < 4; mt++)
                #pragma unroll
                for (int nt = 0; nt < 4; nt++)
                    mma168(acc1[mt][nt], af[mt], bf[nt]);
        }
    }
    __syncthreads();

    // prime W2 chunk0 -> buf0
    {
        const float4* src = (const float4*)g_W2p;
        uint32_t dst = sb + OFF_WB;
        for (int j = tid; j < 528; j += 256) cp16(dst + j * 16, src + j);
        CP_COMMIT();
    }

    // epilogue1: h = tf32(relu(acc + b1)) -> sH pair layout
    float* sHf = sAf;
    #pragma unroll
    for (int mt = 0; mt < 4; mt++) {
        int ra = 16 * mt + qr, rbr = ra + 8;
        #pragma unroll
        for (int nt = 0; nt < 4; nt++) {
            int c0 = cb1 + 8 * nt + 2 * qc;
            float bb0 = sB1[c0], bb1 = sB1[c0 + 1];
            float* d = acc1[mt][nt];
            #pragma unroll
            for (int u = 0; u < 2; u++) {
                int c = c0 + u;
                int g = c >> 3, e = c & 7;
                int idx = 8 * g + 2 * (e & 3) + (e >> 2);
                sHf[ra * (2 * SH_STR2) + idx]  = tf32r(fmaxf(d[u] + (u ? bb1 : bb0), 0.f));
                sHf[rbr * (2 * SH_STR2) + idx] = tf32r(fmaxf(d[2 + u] + (u ? bb1 : bb0), 0.f));
            }
        }
    }

    // ---- GEMM2: 64x128, K=256. Warp grid 2x4: Mw=32, Nw=32 ----
    int wm2 = wid & 1, wn2 = wid >> 1;
    int rb2 = 32 * wm2, cb2 = 32 * wn2;

    float acc2[2][4][4];
    #pragma unroll
    for (int mt = 0; mt < 2; mt++)
        #pragma unroll
        for (int nt = 0; nt < 4; nt++)
            #pragma unroll
            for (int j = 0; j < 4; j++) acc2[mt][nt][j] = 0.f;

    const float2* sHp = (const float2*)sHf;
    for (int kc = 0; kc < 16; kc++) {
        __syncthreads();
        if (kc + 1 < 16) {
            const float4* src = (const float4*)g_W2p + (size_t)(kc + 1) * 528;
            uint32_t dst = sb + OFF_WB + ((kc + 1) & 1) * WBUF_STR;
            for (int j = tid; j < 528; j += 256) cp16(dst + j * 16, src + j);
        }
        CP_COMMIT();
        CP_WAIT1();
        __syncthreads();
        const float2* wb = (const float2*)(smem + OFF_WB + (kc & 1) * WBUF_STR);
        #pragma unroll
        for (int kbl = 0; kbl < 2; kbl++) {
            int aslot = 4 * (2 * kc + kbl) + qc;
            uint32_t af[2][4];
            #pragma unroll
            for (int mt = 0; mt < 2; mt++) {
                float2 a0 = sHp[(rb2 + 16 * mt + qr) * SH_STR2 + aslot];
                float2 a1 = sHp[(rb2 + 16 * mt + 8 + qr) * SH_STR2 + aslot];
                af[mt][0] = __float_as_uint(a0.x); af[mt][1] = __float_as_uint(a1.x);
                af[mt][2] = __float_as_uint(a0.y); af[mt][3] = __float_as_uint(a1.y);
            }
            int srow = 4 * kbl + qc;
            uint32_t bf[4][2];
            #pragma unroll
            for (int nt = 0; nt < 4; nt++) {
                float2 bv = wb[srow * 132 + cb2 + 8 * nt + qr];
                bf[nt][0] = __float_as_uint(bv.x); bf[nt][1] = __float_as_uint(bv.y);
            }
            #pragma unroll
            for (int mt = 0; mt < 2; mt++)
                #pragma unroll
                for (int nt = 0; nt < 4; nt++)
                    mma168(acc2[mt][nt], af[mt], bf[nt]);
        }
    }

    // epilogue2: msg = relu(acc2+b2) (kept in regs); gate dot; ex=exp(logit);
    // denom atomic; fused softmax-numerator scatter red.add(ex*msg) -> g_aggr
    {
        float gpa[2] = {0.f, 0.f}, gpb[2] = {0.f, 0.f};
        #pragma unroll
        for (int mt = 0; mt < 2; mt++) {
            #pragma unroll
            for (int nt = 0; nt < 4; nt++) {
                int c0 = cb2 + 8 * nt + 2 * qc;
                float bb0 = sB2[c0], bb1 = sB2[c0 + 1];
                float w0 = sWg[c0], w1 = sWg[c0 + 1];
                float* d = acc2[mt][nt];
                d[0] = fmaxf(d[0] + bb0, 0.f);
                d[1] = fmaxf(d[1] + bb1, 0.f);
                d[2] = fmaxf(d[2] + bb0, 0.f);
                d[3] = fmaxf(d[3] + bb1, 0.f);
                gpa[mt] += d[0] * w0 + d[1] * w1;
                gpb[mt] += d[2] * w0 + d[3] * w1;
            }
        }
        #pragma unroll
        for (int mt = 0; mt < 2; mt++) {
            gpa[mt] += __shfl_xor_sync(0xffffffffu, gpa[mt], 1);
            gpa[mt] += __shfl_xor_sync(0xffffffffu, gpa[mt], 2);
            gpb[mt] += __shfl_xor_sync(0xffffffffu, gpb[mt], 1);
            gpb[mt] += __shfl_xor_sync(0xffffffffu, gpb[mt], 2);
        }
        if (qc == 0) {
            #pragma unroll
            for (int mt = 0; mt < 2; mt++) {
                sGate[wn2 * 64 + rb2 + 16 * mt + qr] = gpa[mt];
                sGate[wn2 * 64 + rb2 + 16 * mt + 8 + qr] = gpb[mt];
            }
        }
        __syncthreads();
        if (tid < 64 && tid < nE) {
            float lgv = sGate[tid] + sGate[64 + tid] + sGate[128 + tid] + sGate[192 + tid] + __ldg(bg);
            float ex = expf(lgv);                 // no max-shift: cancels in num/denom
            atomicAdd(&g_denom[sR[tid]], ex);
            sGate[tid] = ex;                      // own slot only; re-read after barrier
        }
        __syncthreads();
        #pragma unroll
        for (int mt = 0; mt < 2; mt++) {
            int ra = rb2 + 16 * mt + qr, rbr = ra + 8;
            if (ra < nE) {
                float exa = sGate[ra];
                float* base = g_aggr + (size_t)sR[ra] * MSG;
                #pragma unroll
                for (int nt = 0; nt < 4; nt++) {
                    int c0 = cb2 + 8 * nt + 2 * qc;
                    float* d = acc2[mt][nt];
                    red2(base + c0, exa * d[0], exa * d[1]);
                }
            }
            if (rbr < nE) {
                float exb = sGate[rbr];
                float* base = g_aggr + (size_t)sR[rbr] * MSG;
                #pragma unroll
                for (int nt = 0; nt < 4; nt++) {
                    int c0 = cb2 + 8 * nt + 2 * qc;
                    float* d = acc2[mt][nt];
                    red2(base + c0, exb * d[2], exb * d[3]);
                }
            }
        }
    }
}

// ---------------- agent MLP head (FFMA fp32, fused divide) ----------------
#define SMEM_AG (2 * 64 * HID * 4)
__global__ __launch_bounds__(256) void k_agent(
    const float* __restrict__ Wh1, const float* __restrict__ bh1,
    const float* __restrict__ Wh2, const float* __restrict__ bh2,
    const float* __restrict__ Wo,  const float* __restrict__ bo,
    float* __restrict__ out)
{
    extern __shared__ float smemf[];
    float* s1 = smemf;
    float* s2 = smemf + 64 * HID;
    __shared__ float sInv[64];

    int a0 = blockIdx.x * 64;
    int tid = threadIdx.x;
    int rg = tid >> 5, lane = tid & 31;
    int r0 = rg * 8;

    if (tid < 64) {
        int a = a0 + tid;
        sInv[tid] = (a < N_AGENTS) ? 1.f / (g_denom[a] + 1e-9f) : 0.f;
    }
    __syncthreads();

    for (int j = tid; j < 64 * (MSG / 4); j += 256) {
        int r = j >> 5, c4 = j & 31;
        int a = a0 + r;
        float4 v = (a < N_AGENTS) ? *((const float4*)g_aggr + (size_t)a * (MSG / 4) + c4)
                                  : make_float4(0.f, 0.f, 0.f, 0.f);
        float inv = sInv[r];
        *(float4*)&s2[r * MSG + c4 * 4] = make_float4(v.x * inv, v.y * inv, v.z * inv, v.w * inv);
    }
    __syncthreads();

    {
        int c0 = lane * 8;
        float acc[8][8];
        {
            float4 u0 = __ldg((const float4*)(bh1 + c0));
            float4 u1 = __ldg((const float4*)(bh1 + c0 + 4));
            float bv[8] = {u0.x,u0.y,u0.z,u0.w,u1.x,u1.y,u1.z,u1.w};
            #pragma unroll
            for (int i = 0; i < 8; i++)
                #pragma unroll
                for (int j = 0; j < 8; j++) acc[i][j] = bv[j];
        }
        for (int k4 = 0; k4 < MSG / 4; k4++) {
            float wv[4][8];
            #pragma unroll
            for (int kk = 0; kk < 4; kk++) {
                const float* wr = Wh1 + (k4 * 4 + kk) * HID + c0;
                float4 u0 = __ldg((const float4*)wr);
                float4 u1 = __ldg((const float4*)(wr + 4));
                wv[kk][0]=u0.x; wv[kk][1]=u0.y; wv[kk][2]=u0.z; wv[kk][3]=u0.w;
                wv[kk][4]=u1.x; wv[kk][5]=u1.y; wv[kk][6]=u1.z; wv[kk][7]=u1.w;
            }
            #pragma unroll
            for (int i = 0; i < 8; i++) {
                float4 a = *(float4*)&s2[(r0 + i) * MSG + k4 * 4];
                float av[4] = {a.x, a.y, a.z, a.w};
                #pragma unroll
                for (int kk = 0; kk < 4; kk++)
                    #pragma unroll
                    for (int j = 0; j < 8; j++) acc[i][j] += av[kk] * wv[kk][j];
            }
        }
        #pragma unroll
        for (int i = 0; i < 8; i++) {
            #pragma unroll
            for (int j = 0; j < 8; j++) acc[i][j] = fmaxf(acc[i][j], 0.f);
            *(float4*)&s1[(r0 + i) * HID + c0]     = make_float4(acc[i][0], acc[i][1], acc[i][2], acc[i][3]);
            *(float4*)&s1[(r0 + i) * HID + c0 + 4] = make_float4(acc[i][4], acc[i][5], acc[i][6], acc[i][7]);
        }
    }
    __syncthreads();

    {
        int c0 = lane * 8;
        float acc[8][8];
        {
            float4 u0 = __ldg((const float4*)(bh2 + c0));
            float4 u1 = __ldg((const float4*)(bh2 + c0 + 4));
            float bv[8] = {u0.x,u0.y,u0.z,u0.w,u1.x,u1.y,u1.z,u1.w};
            #pragma unroll
            for (int i = 0; i < 8; i++)
                #pragma unroll
                for (int j = 0; j < 8; j++) acc[i][j] = bv[j];
        }
        for (int k4 = 0; k4 < HID / 4; k4++) {
            float wv[4][8];
            #pragma unroll
            for (int kk = 0; kk < 4; kk++) {
                const float* wr = Wh2 + (k4 * 4 + kk) * HID + c0;
                float4 u0 = __ldg((const float4*)wr);
                float4 u1 = __ldg((const float4*)(wr + 4));
                wv[kk][0]=u0.x; wv[kk][1]=u0.y; wv[kk][2]=u0.z; wv[kk][3]=u0.w;
                wv[kk][4]=u1.x; wv[kk][5]=u1.y; wv[kk][6]=u1.z; wv[kk][7]=u1.w;
            }
            #pragma unroll
            for (int i = 0; i < 8; i++) {
                float4 a = *(float4*)&s1[(r0 + i) * HID + k4 * 4];
                float av[4] = {a.x, a.y, a.z, a.w};
                #pragma unroll
                for (int kk = 0; kk < 4; kk++)
                    #pragma unroll
                    for (int j = 0; j < 8; j++) acc[i][j] += av[kk] * wv[kk][j];
            }
        }
        __syncthreads();
        #pragma unroll
        for (int i = 0; i < 8; i++) {
            #pragma unroll
            for (int j = 0; j < 8; j++) acc[i][j] = fmaxf(acc[i][j], 0.f);
            *(float4*)&s2[(r0 + i) * HID + c0]     = make_float4(acc[i][0], acc[i][1], acc[i][2], acc[i][3]);
            *(float4*)&s2[(r0 + i) * HID + c0 + 4] = make_float4(acc[i][4], acc[i][5], acc[i][6], acc[i][7]);
        }
    }
    __syncthreads();

    {
        float wv[8];
        #pragma unroll
        for (int j = 0; j < 8; j++) wv[j] = __ldg(Wo + lane + 32 * j);
        float bov = __ldg(bo);
        #pragma unroll
        for (int i = 0; i < 8; i++) {
            int rw = r0 + i;
            float p = 0.f;
            #pragma unroll
            for (int j = 0; j < 8; j++) p += s2[rw * HID + lane + 32 * j] * wv[j];
            #pragma unroll
            for (int off = 16; off > 0; off >>= 1) p += __shfl_xor_sync(0xffffffffu, p, off);
            int a = a0 + rw;
            if (lane == 0 && a < N_AGENTS) out[a] = tanhf(p + bov);
        }
    }
}

// ---------------- launch ----------------
extern "C" void kernel_launch(void* const* d_in, const int* in_sizes, int n_in,
                              void* d_out, int out_size)
{
    const float* node = (const float*)d_in[0];
    const float* ef   = (const float*)d_in[1];
    const float* W1   = (const float*)d_in[2];
    const float* b1   = (const float*)d_in[3];
    const float* W2   = (const float*)d_in[4];
    const float* b2   = (const float*)d_in[5];
    const float* wg   = (const float*)d_in[6];
    const float* bg   = (const float*)d_in[7];
    const float* Wh1  = (const float*)d_in[8];
    const float* bh1  = (const float*)d_in[9];
    const float* Wh2  = (const float*)d_in[10];
    const float* bh2  = (const float*)d_in[11];
    const float* Wo   = (const float*)d_in[12];
    const float* bo   = (const float*)d_in[13];
    const int*   snd  = (const int*)d_in[14];
    const int*   rcv  = (const int*)d_in[15];
    float* out = (float*)d_out;

    cudaFuncSetAttribute(k_edge_mma, cudaFuncAttributeMaxDynamicSharedMemorySize, SMEM_EDGE);
    cudaFuncSetAttribute(k_agent,    cudaFuncAttributeMaxDynamicSharedMemorySize, SMEM_AG);

    k_init<<<12500, 256>>>();
    k_compact<<<(N_EDGESC + 255) / 256, 256>>>(rcv);
    k_prep<<<(160 * 256 + 256 * 128 + 255) / 256, 256>>>(W1, W2);
    k_edge_mma<<<(N_EDGESC + 63) / 64, 256, SMEM_EDGE>>>(node, ef, b1, b2, wg, bg, snd, rcv);
    k_agent<<<(N_AGENTS + 63) / 64, 256, SMEM_AG>>>(Wh1, bh1, Wh2, bh2, Wo, bo, out);
}

// round 10
// speedup vs baseline: 2.3273x; 1.1691x over previous
#include <cuda_runtime.h>
#include <math.h>
#include <stdint.h>

#define N_NODES  50000
#define N_EDGESC 800000
#define ND       64
#define ED       32
#define MSG      128
#define HID      256
#define N_AGENTS 25000

// ---------------- scratch ----------------
__device__ int          g_eidx[N_EDGESC];
__device__ int          g_cnt;
__device__ float        g_denom[N_AGENTS];
__device__ float        g_aggr[(size_t)N_AGENTS * MSG];
// fragment-major tf32 weights: one float2 per (lane) per (warp-col, kgroup, ntile)
// layout matches mma.m16n8k8 B-fragment registers exactly
__device__ __align__(16) float2 g_W1f[8 * 20 * 4 * 32];   // 163840 B
__device__ __align__(16) float2 g_W2f[4 * 32 * 4 * 32];   // 131072 B

__device__ __forceinline__ float tf32r(float x) {
    uint32_t u;
    asm("cvt.rna.tf32.f32 %0, %1;" : "=r"(u) : "f"(x));
    return __uint_as_float(u);
}
__device__ __forceinline__ void mma168(float* d, const uint32_t* a, const uint32_t* b) {
    asm volatile(
        "mma.sync.aligned.m16n8k8.row.col.f32.tf32.tf32.f32 "
        "{%0,%1,%2,%3}, {%4,%5,%6,%7}, {%8,%9}, {%0,%1,%2,%3};"
        : "+f"(d[0]), "+f"(d[1]), "+f"(d[2]), "+f"(d[3])
        : "r"(a[0]), "r"(a[1]), "r"(a[2]), "r"(a[3]), "r"(b[0]), "r"(b[1]));
}
__device__ __forceinline__ void red2(float* dst, float x, float y) {
    asm volatile("red.global.add.v2.f32 [%0], {%1,%2};" :: "l"(dst), "f"(x), "f"(y) : "memory");
}

// ---------------- init / compact / prep ----------------
__global__ void k_init() {
    int i = blockIdx.x * blockDim.x + threadIdx.x;
    int stride = gridDim.x * blockDim.x;
    for (int j = i; j < N_AGENTS * MSG; j += stride) g_aggr[j] = 0.f;
    if (i < N_AGENTS) g_denom[i] = 0.f;
    if (i == 0) g_cnt = 0;
}
__global__ void k_compact(const int* __restrict__ rcv) {
    int e = blockIdx.x * blockDim.x + threadIdx.x;
    if (e < N_EDGESC && rcv[e] < N_AGENTS) {
        int p = atomicAdd(&g_cnt, 1);
        g_eidx[p] = e;
    }
}
// fragment-major weight prep: g_W1f[((wn*20+kg)*4+nt)*32+lane] =
//   ( W1[8kg+qc][32wn+8nt+qr], W1[8kg+qc+4][32wn+8nt+qr] )
__global__ void k_prep(const float* __restrict__ W1, const float* __restrict__ W2) {
    int i = blockIdx.x * blockDim.x + threadIdx.x;
    if (i < 8 * 20 * 4 * 32) {
        int lane = i & 31, nt = (i >> 5) & 3, kg = (i >> 7) % 20, wn = i / (20 * 4 * 32);
        int qr = lane >> 2, qc = lane & 3;
        int n = 32 * wn + 8 * nt + qr;
        int k0 = 8 * kg + qc;
        g_W1f[i] = make_float2(tf32r(W1[(size_t)k0 * HID + n]),
                               tf32r(W1[(size_t)(k0 + 4) * HID + n]));
    }
    int j = i - 8 * 20 * 4 * 32;
    if (j >= 0 && j < 4 * 32 * 4 * 32) {
        int lane = j & 31, nt = (j >> 5) & 3, kg = (j >> 7) & 31, wn = j / (32 * 4 * 32);
        int qr = lane >> 2, qc = lane & 3;
        int n = 32 * wn + 8 * nt + qr;
        int k0 = 8 * kg + qc;
        g_W2f[j] = make_float2(tf32r(W2[(size_t)k0 * MSG + n]),
                               tf32r(W2[(size_t)(k0 + 4) * MSG + n]));
    }
}

// ---------------- fused edge MLP + softmax-numerator scatter ----------------
#define SA_STR2  84             // sA pair row stride (float2); 672 B/row (mod 128 = 32)
#define SH_STR2  132            // sH pair row stride (float2); 1056 B/row
#define OFF_AH   0              // union: sA 43008 / sH 67584
#define OFF_EG   67584
#define OFF_S    67840
#define OFF_R    68096
#define OFF_B1   68352          // 256 f
#define OFF_B2   69376          // 128 f
#define OFF_WG   69888          // 128 f
#define OFF_GATE 70400          // 4 x 64 f
#define SMEM_EDGE 71424

__global__ __launch_bounds__(256, 2) void k_edge_mma(
    const float* __restrict__ nf, const float* __restrict__ ef,
    const float* __restrict__ b1, const float* __restrict__ b2,
    const float* __restrict__ wg, const float* __restrict__ bg,
    const int* __restrict__ snd, const int* __restrict__ rcv)
{
    extern __shared__ char smem[];
    float* sAf = (float*)(smem + OFF_AH);
    int*   sEg = (int*)(smem + OFF_EG);
    int*   sS  = (int*)(smem + OFF_S);
    int*   sR  = (int*)(smem + OFF_R);
    float* sB1 = (float*)(smem + OFF_B1);
    float* sB2 = (float*)(smem + OFF_B2);
    float* sWg = (float*)(smem + OFF_WG);
    float* sGate = (float*)(smem + OFF_GATE);

    int cnt = g_cnt;
    int ci0 = blockIdx.x * 64;
    if (ci0 >= cnt) return;
    int nE = min(64, cnt - ci0);

    int tid = threadIdx.x;
    int wid = tid >> 5, lane = tid & 31;
    int qr = lane >> 2, qc = lane & 3;

    if (tid < 64) {
        int e = (tid < nE) ? g_eidx[ci0 + tid] : g_eidx[ci0];
        sEg[tid] = e;
        sS[tid] = snd[e];
        sR[tid] = rcv[e];
    }
    sB1[tid] = __ldg(b1 + tid);
    if (tid < 128) { sB2[tid] = __ldg(b2 + tid); sWg[tid] = __ldg(wg + tid); }
    __syncthreads();

    // gather A tile [nf[s]|nf[r]|ef] into pair layout
    for (int i = tid; i < 64 * 40; i += 256) {
        int r = i / 40, q = i % 40;
        float4 v;
        int cb;
        if (q < 16)      { v = __ldg((const float4*)(nf + (size_t)sS[r] * ND) + q);         cb = 4 * q; }
        else if (q < 32) { v = __ldg((const float4*)(nf + (size_t)sR[r] * ND) + (q - 16));  cb = 64 + 4 * (q - 16); }
        else             { v = __ldg((const float4*)(ef + (size_t)sEg[r] * ED) + (q - 32)); cb = 128 + 4 * (q - 32); }
        int g = cb >> 3, comp = (cb >> 2) & 1;
        float* p = sAf + r * (2 * SA_STR2) + 8 * g + comp;
        p[0] = tf32r(v.x); p[2] = tf32r(v.y); p[4] = tf32r(v.z); p[6] = tf32r(v.w);
    }
    __syncthreads();

    // ---- GEMM1: 64x256, K=160. Warp grid 1x8: Mw=64, Nw=32. B from L2 (frag-major) ----
    float acc1[4][4][4];
    #pragma unroll
    for (int mt = 0; mt < 4; mt++)
        #pragma unroll
        for (int nt = 0; nt < 4; nt++)
            #pragma unroll
            for (int j = 0; j < 4; j++) acc1[mt][nt][j] = 0.f;

    {
        const float2* sAp = (const float2*)sAf;
        const float2* wf = g_W1f + (size_t)wid * (20 * 4 * 32) + lane;
        float2 bcur[4], bnxt[4];
        #pragma unroll
        for (int nt = 0; nt < 4; nt++) bcur[nt] = __ldg(wf + nt * 32);

        for (int kg = 0; kg < 20; kg++) {
            if (kg + 1 < 20) {
                #pragma unroll
                for (int nt = 0; nt < 4; nt++) bnxt[nt] = __ldg(wf + (kg + 1) * 128 + nt * 32);
            }
            int aslot = 4 * kg + qc;
            uint32_t af[4][4];
            #pragma unroll
            for (int mt = 0; mt < 4; mt++) {
                float2 a0 = sAp[(16 * mt + qr) * SA_STR2 + aslot];
                float2 a1 = sAp[(16 * mt + 8 + qr) * SA_STR2 + aslot];
                af[mt][0] = __float_as_uint(a0.x); af[mt][1] = __float_as_uint(a1.x);
                af[mt][2] = __float_as_uint(a0.y); af[mt][3] = __float_as_uint(a1.y);
            }
            uint32_t bf[4][2];
            #pragma unroll
            for (int nt = 0; nt < 4; nt++) {
                bf[nt][0] = __float_as_uint(bcur[nt].x);
                bf[nt][1] = __float_as_uint(bcur[nt].y);
            }
            #pragma unroll
            for (int mt = 0; mt < 4; mt++)
                #pragma unroll
                for (int nt = 0; nt < 4; nt++)
                    mma168(acc1[mt][nt], af[mt], bf[nt]);
            #pragma unroll
            for (int nt = 0; nt < 4; nt++) bcur[nt] = bnxt[nt];
        }
    }
    __syncthreads();   // all GEMM1 reads of sA done before sH overwrite

    // epilogue1: h = tf32(relu(acc + b1)) -> sH pair layout
    int cb1 = 32 * wid;
    float* sHf = sAf;
    #pragma unroll
    for (int mt = 0; mt < 4; mt++) {
        int ra = 16 * mt + qr, rbr = ra + 8;
        #pragma unroll
        for (int nt = 0; nt < 4; nt++) {
            int c0 = cb1 + 8 * nt + 2 * qc;
            float bb0 = sB1[c0], bb1 = sB1[c0 + 1];
            float* d = acc1[mt][nt];
            #pragma unroll
            for (int u = 0; u < 2; u++) {
                int c = c0 + u;
                int g = c >> 3, e = c & 7;
                int idx = 8 * g + 2 * (e & 3) + (e >> 2);
                sHf[ra * (2 * SH_STR2) + idx]  = tf32r(fmaxf(d[u] + (u ? bb1 : bb0), 0.f));
                sHf[rbr * (2 * SH_STR2) + idx] = tf32r(fmaxf(d[2 + u] + (u ? bb1 : bb0), 0.f));
            }
        }
    }
    __syncthreads();

    // ---- GEMM2: 64x128, K=256. Warp grid 2x4: Mw=32, Nw=32. B from L2 (frag-major) ----
    int wm2 = wid & 1, wn2 = wid >> 1;
    int rb2 = 32 * wm2, cb2 = 32 * wn2;

    float acc2[2][4][4];
    #pragma unroll
    for (int mt = 0; mt < 2; mt++)
        #pragma unroll
        for (int nt = 0; nt < 4; nt++)
            #pragma unroll
            for (int j = 0; j < 4; j++) acc2[mt][nt][j] = 0.f;

    {
        const float2* sHp = (const float2*)sHf;
        const float2* wf = g_W2f + (size_t)wn2 * (32 * 4 * 32) + lane;
        float2 bcur[4], bnxt[4];
        #pragma unroll
        for (int nt = 0; nt < 4; nt++) bcur[nt] = __ldg(wf + nt * 32);

        for (int kg = 0; kg < 32; kg++) {
            if (kg + 1 < 32) {
                #pragma unroll
                for (int nt = 0; nt < 4; nt++) bnxt[nt] = __ldg(wf + (kg + 1) * 128 + nt * 32);
            }
            int aslot = 4 * kg + qc;
            uint32_t af[2][4];
            #pragma unroll
            for (int mt = 0; mt < 2; mt++) {
                float2 a0 = sHp[(rb2 + 16 * mt + qr) * SH_STR2 + aslot];
                float2 a1 = sHp[(rb2 + 16 * mt + 8 + qr) * SH_STR2 + aslot];
                af[mt][0] = __float_as_uint(a0.x); af[mt][1] = __float_as_uint(a1.x);
                af[mt][2] = __float_as_uint(a0.y); af[mt][3] = __float_as_uint(a1.y);
            }
            uint32_t bf[4][2];
            #pragma unroll
            for (int nt = 0; nt < 4; nt++) {
                bf[nt][0] = __float_as_uint(bcur[nt].x);
                bf[nt][1] = __float_as_uint(bcur[nt].y);
            }
            #pragma unroll
            for (int mt = 0; mt < 2; mt++)
                #pragma unroll
                for (int nt = 0; nt < 4; nt++)
                    mma168(acc2[mt][nt], af[mt], bf[nt]);
            #pragma unroll
            for (int nt = 0; nt < 4; nt++) bcur[nt] = bnxt[nt];
        }
    }

    // epilogue2: msg = relu(acc2+b2); gate dot; ex=exp(logit); denom atomic; red scatter
    {
        float gpa[2] = {0.f, 0.f}, gpb[2] = {0.f, 0.f};
        #pragma unroll
        for (int mt = 0; mt < 2; mt++) {
            #pragma unroll
            for (int nt = 0; nt < 4; nt++) {
                int c0 = cb2 + 8 * nt + 2 * qc;
                float bb0 = sB2[c0], bb1 = sB2[c0 + 1];
                float w0 = sWg[c0], w1 = sWg[c0 + 1];
                float* d = acc2[mt][nt];
                d[0] = fmaxf(d[0] + bb0, 0.f);
                d[1] = fmaxf(d[1] + bb1, 0.f);
                d[2] = fmaxf(d[2] + bb0, 0.f);
                d[3] = fmaxf(d[3] + bb1, 0.f);
                gpa[mt] += d[0] * w0 + d[1] * w1;
                gpb[mt] += d[2] * w0 + d[3] * w1;
            }
        }
        #pragma unroll
        for (int mt = 0; mt < 2; mt++) {
            gpa[mt] += __shfl_xor_sync(0xffffffffu, gpa[mt], 1);
            gpa[mt] += __shfl_xor_sync(0xffffffffu, gpa[mt], 2);
            gpb[mt] += __shfl_xor_sync(0xffffffffu, gpb[mt], 1);
            gpb[mt] += __shfl_xor_sync(0xffffffffu, gpb[mt], 2);
        }
        if (qc == 0) {
            #pragma unroll
            for (int mt = 0; mt < 2; mt++) {
                sGate[wn2 * 64 + rb2 + 16 * mt + qr] = gpa[mt];
                sGate[wn2 * 64 + rb2 + 16 * mt + 8 + qr] = gpb[mt];
            }
        }
        __syncthreads();
        if (tid < 64 && tid < nE) {
            float lgv = sGate[tid] + sGate[64 + tid] + sGate[128 + tid] + sGate[192 + tid] + __ldg(bg);
            float ex = expf(lgv);                 // no max-shift: cancels in num/denom
            atomicAdd(&g_denom[sR[tid]], ex);
            sGate[tid] = ex;
        }
        __syncthreads();
        #pragma unroll
        for (int mt = 0; mt < 2; mt++) {
            int ra = rb2 + 16 * mt + qr, rbr = ra + 8;
            if (ra < nE) {
                float exa = sGate[ra];
                float* base = g_aggr + (size_t)sR[ra] * MSG;
                #pragma unroll
                for (int nt = 0; nt < 4; nt++) {
                    int c0 = cb2 + 8 * nt + 2 * qc;
                    float* d = acc2[mt][nt];
                    red2(base + c0, exa * d[0], exa * d[1]);
                }
            }
            if (rbr < nE) {
                float exb = sGate[rbr];
                float* base = g_aggr + (size_t)sR[rbr] * MSG;
                #pragma unroll
                for (int nt = 0; nt < 4; nt++) {
                    int c0 = cb2 + 8 * nt + 2 * qc;
                    float* d = acc2[mt][nt];
                    red2(base + c0, exb * d[2], exb * d[3]);
                }
            }
        }
    }
}

// ---------------- agent MLP head (FFMA fp32, fused divide) ----------------
#define SMEM_AG (2 * 64 * HID * 4)
__global__ __launch_bounds__(256) void k_agent(
    const float* __restrict__ Wh1, const float* __restrict__ bh1,
    const float* __restrict__ Wh2, const float* __restrict__ bh2,
    const float* __restrict__ Wo,  const float* __restrict__ bo,
    float* __restrict__ out)
{
    extern __shared__ float smemf[];
    float* s1 = smemf;
    float* s2 = smemf + 64 * HID;
    __shared__ float sInv[64];

    int a0 = blockIdx.x * 64;
    int tid = threadIdx.x;
    int rg = tid >> 5, lane = tid & 31;
    int r0 = rg * 8;

    if (tid < 64) {
        int a = a0 + tid;
        sInv[tid] = (a < N_AGENTS) ? 1.f / (g_denom[a] + 1e-9f) : 0.f;
    }
    __syncthreads();

    for (int j = tid; j < 64 * (MSG / 4); j += 256) {
        int r = j >> 5, c4 = j & 31;
        int a = a0 + r;
        float4 v = (a < N_AGENTS) ? *((const float4*)g_aggr + (size_t)a * (MSG / 4) + c4)
                                  : make_float4(0.f, 0.f, 0.f, 0.f);
        float inv = sInv[r];
        *(float4*)&s2[r * MSG + c4 * 4] = make_float4(v.x * inv, v.y * inv, v.z * inv, v.w * inv);
    }
    __syncthreads();

    {
        int c0 = lane * 8;
        float acc[8][8];
        {
            float4 u0 = __ldg((const float4*)(bh1 + c0));
            float4 u1 = __ldg((const float4*)(bh1 + c0 + 4));
            float bv[8] = {u0.x,u0.y,u0.z,u0.w,u1.x,u1.y,u1.z,u1.w};
            #pragma unroll
            for (int i = 0; i < 8; i++)
                #pragma unroll
                for (int j = 0; j < 8; j++) acc[i][j] = bv[j];
        }
        for (int k4 = 0; k4 < MSG / 4; k4++) {
            float wv[4][8];
            #pragma unroll
            for (int kk = 0; kk < 4; kk++) {
                const float* wr = Wh1 + (k4 * 4 + kk) * HID + c0;
                float4 u0 = __ldg((const float4*)wr);
                float4 u1 = __ldg((const float4*)(wr + 4));
                wv[kk][0]=u0.x; wv[kk][1]=u0.y; wv[kk][2]=u0.z; wv[kk][3]=u0.w;
                wv[kk][4]=u1.x; wv[kk][5]=u1.y; wv[kk][6]=u1.z; wv[kk][7]=u1.w;
            }
            #pragma unroll
            for (int i = 0; i < 8; i++) {
                float4 a = *(float4*)&s2[(r0 + i) * MSG + k4 * 4];
                float av[4] = {a.x, a.y, a.z, a.w};
                #pragma unroll
                for (int kk = 0; kk < 4; kk++)
                    #pragma unroll
                    for (int j = 0; j < 8; j++) acc[i][j] += av[kk] * wv[kk][j];
            }
        }
        #pragma unroll
        for (int i = 0; i < 8; i++) {
            #pragma unroll
            for (int j = 0; j < 8; j++) acc[i][j] = fmaxf(acc[i][j], 0.f);
            *(float4*)&s1[(r0 + i) * HID + c0]     = make_float4(acc[i][0], acc[i][1], acc[i][2], acc[i][3]);
            *(float4*)&s1[(r0 + i) * HID + c0 + 4] = make_float4(acc[i][4], acc[i][5], acc[i][6], acc[i][7]);
        }
    }
    __syncthreads();

    {
        int c0 = lane * 8;
        float acc[8][8];
        {
            float4 u0 = __ldg((const float4*)(bh2 + c0));
            float4 u1 = __ldg((const float4*)(bh2 + c0 + 4));
            float bv[8] = {u0.x,u0.y,u0.z,u0.w,u1.x,u1.y,u1.z,u1.w};
            #pragma unroll
            for (int i = 0; i < 8; i++)
                #pragma unroll
                for (int j = 0; j < 8; j++) acc[i][j] = bv[j];
        }
        for (int k4 = 0; k4 < HID / 4; k4++) {
            float wv[4][8];
            #pragma unroll
            for (int kk = 0; kk < 4; kk++) {
                const float* wr = Wh2 + (k4 * 4 + kk) * HID + c0;
                float4 u0 = __ldg((const float4*)wr);
                float4 u1 = __ldg((const float4*)(wr + 4));
                wv[kk][0]=u0.x; wv[kk][1]=u0.y; wv[kk][2]=u0.z; wv[kk][3]=u0.w;
                wv[kk][4]=u1.x; wv[kk][5]=u1.y; wv[kk][6]=u1.z; wv[kk][7]=u1.w;
            }
            #pragma unroll
            for (int i = 0; i < 8; i++) {
                float4 a = *(float4*)&s1[(r0 + i) * HID + k4 * 4];
                float av[4] = {a.x, a.y, a.z, a.w};
                #pragma unroll
                for (int kk = 0; kk < 4; kk++)
                    #pragma unroll
                    for (int j = 0; j < 8; j++) acc[i][j] += av[kk] * wv[kk][j];
            }
        }
        __syncthreads();
        #pragma unroll
        for (int i = 0; i < 8; i++) {
            #pragma unroll
            for (int j = 0; j < 8; j++) acc[i][j] = fmaxf(acc[i][j], 0.f);
            *(float4*)&s2[(r0 + i) * HID + c0]     = make_float4(acc[i][0], acc[i][1], acc[i][2], acc[i][3]);
            *(float4*)&s2[(r0 + i) * HID + c0 + 4] = make_float4(acc[i][4], acc[i][5], acc[i][6], acc[i][7]);
        }
    }
    __syncthreads();

    {
        float wv[8];
        #pragma unroll
        for (int j = 0; j < 8; j++) wv[j] = __ldg(Wo + lane + 32 * j);
        float bov = __ldg(bo);
        #pragma unroll
        for (int i = 0; i < 8; i++) {
            int rw = r0 + i;
            float p = 0.f;
            #pragma unroll
            for (int j = 0; j < 8; j++) p += s2[rw * HID + lane + 32 * j] * wv[j];
            #pragma unroll
            for (int off = 16; off > 0; off >>= 1) p += __shfl_xor_sync(0xffffffffu, p, off);
            int a = a0 + rw;
            if (lane == 0 && a < N_AGENTS) out[a] = tanhf(p + bov);
        }
    }
}

// ---------------- launch ----------------
extern "C" void kernel_launch(void* const* d_in, const int* in_sizes, int n_in,
                              void* d_out, int out_size)
{
    const float* node = (const float*)d_in[0];
    const float* ef   = (const float*)d_in[1];
    const float* W1   = (const float*)d_in[2];
    const float* b1   = (const float*)d_in[3];
    const float* W2   = (const float*)d_in[4];
    const float* b2   = (const float*)d_in[5];
    const float* wg   = (const float*)d_in[6];
    const float* bg   = (const float*)d_in[7];
    const float* Wh1  = (const float*)d_in[8];
    const float* bh1  = (const float*)d_in[9];
    const float* Wh2  = (const float*)d_in[10];
    const float* bh2  = (const float*)d_in[11];
    const float* Wo   = (const float*)d_in[12];
    const float* bo   = (const float*)d_in[13];
    const int*   snd  = (const int*)d_in[14];
    const int*   rcv  = (const int*)d_in[15];
    float* out = (float*)d_out;

    cudaFuncSetAttribute(k_edge_mma, cudaFuncAttributeMaxDynamicSharedMemorySize, SMEM_EDGE);
    cudaFuncSetAttribute(k_agent,    cudaFuncAttributeMaxDynamicSharedMemorySize, SMEM_AG);

    k_init<<<12500, 256>>>();
    k_compact<<<(N_EDGESC + 255) / 256, 256>>>(rcv);
    k_prep<<<(8 * 20 * 4 * 32 + 4 * 32 * 4 * 32 + 255) / 256, 256>>>(W1, W2);
    k_edge_mma<<<(N_EDGESC + 63) / 64, 256, SMEM_EDGE>>>(node, ef, b1, b2, wg, bg, snd, rcv);
    k_agent<<<(N_AGENTS + 63) / 64, 256, SMEM_AG>>>(Wh1, bh1, Wh2, bh2, Wo, bo, out);
}